// round 2
// baseline (speedup 1.0000x reference)
#include <cuda_runtime.h>
#include <math.h>

// ---------------------------------------------------------------------------
// GNN_Encoder: 3x GCNConv (with self-loops, sym-norm) + LN/leaky/residual + tanh
// Shapes: B=64, N=10000, F=16, H=64, E=320000
// Strategy:
//   * layout [node][batch][feat] so aggregation rows are contiguous
//   * conv1 rewritten as (A x) W1 (aggregate 16 cols, not 64)
//   * norm = dinv[s]*dinv[d] split: pre-scale in GEMM epilogue, post-scale in agg
//   * CSR (by dst) rebuilt each launch; agg = pure sum, no atomics on fat data
//   * GEMMs: persistent warps, 64x64 weights in 128 registers, shfl-broadcast input
// ---------------------------------------------------------------------------

namespace {
constexpr int NA = 10000;          // nodes
constexpr int NF = 16;             // input features
constexpr int HD = 64;             // hidden
constexpr int BT = 64;             // batch
constexpr int MR = NA * BT;        // 640000 rows
constexpr int CH = BT * HD;        // 4096 cols (hidden)
constexpr int CF = BT * NF;        // 1024 cols (input)
constexpr int EMAX = 330000;       // E + N self loops
}

// scratch (device globals; no allocation allowed)
__device__ __align__(256) float g_h1[MR * HD];
__device__ __align__(256) float g_bufA[MR * HD];
__device__ __align__(256) float g_bufB[MR * HD];
__device__ __align__(256) float g_X[NA * CF];
__device__ __align__(256) float g_AX[NA * CF];
__device__ int   g_deg[NA];
__device__ float g_dinv[NA];
__device__ int   g_rowptr[NA + 1];
__device__ int   g_fillptr[NA];
__device__ int   g_col[EMAX];

__device__ __forceinline__ float warp_sum(float v) {
#pragma unroll
    for (int off = 16; off > 0; off >>= 1)
        v += __shfl_xor_sync(0xffffffffu, v, off);
    return v;
}

__device__ __forceinline__ float leaky(float x) {
    return x >= 0.f ? x : 0.01f * x;
}

// ---------------- graph preprocessing ----------------

__global__ void init_deg_kernel() {
    int i = blockIdx.x * blockDim.x + threadIdx.x;
    if (i < NA) g_deg[i] = 1;   // self loop
}

__global__ void count_kernel(const int* __restrict__ ei, int E) {
    int i = blockIdx.x * blockDim.x + threadIdx.x;
    if (i < E) atomicAdd(&g_deg[ei[E + i]], 1);   // dst row
}

__global__ void dinv_kernel() {
    int i = blockIdx.x * blockDim.x + threadIdx.x;
    if (i < NA) g_dinv[i] = rsqrtf((float)g_deg[i]);
}

// single-block exclusive scan of deg -> rowptr (and fillptr = rowptr copy)
__global__ void scan_kernel() {
    __shared__ int sh[1024];
    __shared__ int carry_s;
    int tid = threadIdx.x;
    if (tid == 0) { carry_s = 0; g_rowptr[0] = 0; }
    __syncthreads();
    for (int ch = 0; ch < (NA + 1023) / 1024; ++ch) {
        int i = ch * 1024 + tid;
        int v = (i < NA) ? g_deg[i] : 0;
        sh[tid] = v;
        __syncthreads();
#pragma unroll
        for (int off = 1; off < 1024; off <<= 1) {
            int add = (tid >= off) ? sh[tid - off] : 0;
            __syncthreads();
            sh[tid] += add;
            __syncthreads();
        }
        int incl = sh[tid];
        int carry = carry_s;
        if (i < NA) {
            g_rowptr[i + 1] = carry + incl;
            g_fillptr[i]    = carry + incl - v;
        }
        __syncthreads();
        if (tid == 1023) carry_s = carry + incl;
        __syncthreads();
    }
}

__global__ void fill_kernel(const int* __restrict__ ei, int E) {
    int i = blockIdx.x * blockDim.x + threadIdx.x;
    if (i < E) {
        int d = ei[E + i];
        int pos = atomicAdd(&g_fillptr[d], 1);
        g_col[pos] = ei[i];
    } else if (i < E + NA) {
        int n = i - E;
        int pos = atomicAdd(&g_fillptr[n], 1);
        g_col[pos] = n;
    }
}

// ---------------- transpose + pre-scale: state[b, n*16+f] -> X[n, b, f] * dinv[n]
__global__ void transpose_kernel(const float* __restrict__ state) {
    int i = blockIdx.x * blockDim.x + threadIdx.x;
    if (i < NA * CF) {
        int f = i & 15;
        int b = (i >> 4) & 63;
        int n = i >> 10;
        g_X[i] = state[(size_t)b * (NA * NF) + n * NF + f] * g_dinv[n];
    }
}

// ---------------- aggregation (SpMM): dst[d] = dinv[d] * sum_{s in adj(d)} src[s]
// MODE 0: plain (conv1 pre-GEMM, COLS=1024)
// MODE 1: + b2, leaky, + h1 residual (conv2 epilogue, COLS=4096)
// MODE 2: + b3 (conv3, LN done separately, COLS=4096)
template <int MODE, int COLS>
__global__ __launch_bounds__(128) void agg_kernel(
    const float* __restrict__ src, float* __restrict__ dst,
    const float* __restrict__ bias)
{
    const int d    = blockIdx.x;
    const int base = blockIdx.y * 1024;
    const int t    = threadIdx.x;
    const int c0   = base + t * 4;
    const int c1   = base + 512 + t * 4;

    float4 a0 = make_float4(0.f, 0.f, 0.f, 0.f);
    float4 a1 = make_float4(0.f, 0.f, 0.f, 0.f);

    const int beg = g_rowptr[d], end = g_rowptr[d + 1];
#pragma unroll 4
    for (int j = beg; j < end; ++j) {
        const int s = g_col[j];
        const float* row = src + (size_t)s * COLS;
        float4 u0 = *reinterpret_cast<const float4*>(row + c0);
        float4 u1 = *reinterpret_cast<const float4*>(row + c1);
        a0.x += u0.x; a0.y += u0.y; a0.z += u0.z; a0.w += u0.w;
        a1.x += u1.x; a1.y += u1.y; a1.z += u1.z; a1.w += u1.w;
    }

    const float sc = g_dinv[d];
    float4* op0 = reinterpret_cast<float4*>(dst + (size_t)d * COLS + c0);
    float4* op1 = reinterpret_cast<float4*>(dst + (size_t)d * COLS + c1);

    if (MODE == 0) {
        *op0 = make_float4(a0.x * sc, a0.y * sc, a0.z * sc, a0.w * sc);
        *op1 = make_float4(a1.x * sc, a1.y * sc, a1.z * sc, a1.w * sc);
    } else {
        const float4 bb = *reinterpret_cast<const float4*>(bias + (c0 & 63));
        float4 r0 = make_float4(fmaf(a0.x, sc, bb.x), fmaf(a0.y, sc, bb.y),
                                fmaf(a0.z, sc, bb.z), fmaf(a0.w, sc, bb.w));
        float4 r1 = make_float4(fmaf(a1.x, sc, bb.x), fmaf(a1.y, sc, bb.y),
                                fmaf(a1.z, sc, bb.z), fmaf(a1.w, sc, bb.w));
        if (MODE == 1) {
            const float4 h0 = *reinterpret_cast<const float4*>(g_h1 + (size_t)d * CH + c0);
            const float4 h1v = *reinterpret_cast<const float4*>(g_h1 + (size_t)d * CH + c1);
            r0 = make_float4(leaky(r0.x) + h0.x, leaky(r0.y) + h0.y,
                             leaky(r0.z) + h0.z, leaky(r0.w) + h0.w);
            r1 = make_float4(leaky(r1.x) + h1v.x, leaky(r1.y) + h1v.y,
                             leaky(r1.z) + h1v.z, leaky(r1.w) + h1v.w);
        }
        *op0 = r0;
        *op1 = r1;
    }
}

// ---------------- GEMM K=16 + bias + LayerNorm + leaky -> h1
__global__ __launch_bounds__(128) void gemm16_ln_kernel(
    const float* __restrict__ in, const float* __restrict__ W,
    const float* __restrict__ bias, const float* __restrict__ gma,
    const float* __restrict__ bta, float* __restrict__ out)
{
    const int lane = threadIdx.x & 31;
    float w0[16], w1[16];
#pragma unroll
    for (int f = 0; f < 16; ++f) { w0[f] = W[f * 64 + lane]; w1[f] = W[f * 64 + lane + 32]; }
    const float bb0 = bias[lane], bb1 = bias[lane + 32];
    const float gg0 = gma[lane],  gg1 = gma[lane + 32];
    const float ee0 = bta[lane],  ee1 = bta[lane + 32];

    int warp = (blockIdx.x * blockDim.x + threadIdx.x) >> 5;
    int nw   = (gridDim.x * blockDim.x) >> 5;
    for (int r = warp; r < MR; r += nw) {
        float iv = (lane < 16) ? in[(size_t)r * 16 + lane] : 0.f;
        float a0 = bb0, a1 = bb1;
#pragma unroll
        for (int f = 0; f < 16; ++f) {
            float v = __shfl_sync(0xffffffffu, iv, f);
            a0 = fmaf(v, w0[f], a0);
            a1 = fmaf(v, w1[f], a1);
        }
        float mean = warp_sum(a0 + a1) * (1.f / 64.f);
        float d0 = a0 - mean, d1 = a1 - mean;
        float var = warp_sum(d0 * d0 + d1 * d1) * (1.f / 64.f);
        float rs = rsqrtf(var + 1e-5f);
        float o0 = leaky(d0 * rs * gg0 + ee0);
        float o1 = leaky(d1 * rs * gg1 + ee1);
        out[(size_t)r * 64 + lane]      = o0;
        out[(size_t)r * 64 + lane + 32] = o1;
    }
}

// ---------------- GEMM K=64, epilogue: * dinv[node]  (pre-scale for aggregation)
__global__ __launch_bounds__(128) void gemm64_kernel(
    const float* __restrict__ in, const float* __restrict__ W,
    float* __restrict__ out)
{
    const int lane = threadIdx.x & 31;
    float w0[64], w1[64];
#pragma unroll
    for (int f = 0; f < 64; ++f) { w0[f] = W[f * 64 + lane]; w1[f] = W[f * 64 + lane + 32]; }

    int warp = (blockIdx.x * blockDim.x + threadIdx.x) >> 5;
    int nw   = (gridDim.x * blockDim.x) >> 5;
    for (int r = warp; r < MR; r += nw) {
        const float* rp = in + (size_t)r * 64;
        float in0 = rp[lane], in1 = rp[lane + 32];
        float a0 = 0.f, a1 = 0.f;
#pragma unroll
        for (int f = 0; f < 32; ++f) {
            float v = __shfl_sync(0xffffffffu, in0, f);
            a0 = fmaf(v, w0[f], a0);
            a1 = fmaf(v, w1[f], a1);
        }
#pragma unroll
        for (int f = 0; f < 32; ++f) {
            float v = __shfl_sync(0xffffffffu, in1, f);
            a0 = fmaf(v, w0[32 + f], a0);
            a1 = fmaf(v, w1[32 + f], a1);
        }
        float s = g_dinv[r >> 6];
        float* op = out + (size_t)r * 64;
        op[lane]      = a0 * s;
        op[lane + 32] = a1 * s;
    }
}

// ---------------- LN(g3,be3) + leaky + h1 residual: bufB -> bufA (h3)
__global__ __launch_bounds__(128) void ln_res_kernel(
    const float* __restrict__ gma, const float* __restrict__ bta)
{
    const int lane = threadIdx.x & 31;
    const float gg0 = gma[lane], gg1 = gma[lane + 32];
    const float ee0 = bta[lane], ee1 = bta[lane + 32];
    int warp = (blockIdx.x * blockDim.x + threadIdx.x) >> 5;
    int nw   = (gridDim.x * blockDim.x) >> 5;
    for (int r = warp; r < MR; r += nw) {
        float a0 = g_bufB[(size_t)r * 64 + lane];
        float a1 = g_bufB[(size_t)r * 64 + lane + 32];
        float mean = warp_sum(a0 + a1) * (1.f / 64.f);
        float d0 = a0 - mean, d1 = a1 - mean;
        float var = warp_sum(d0 * d0 + d1 * d1) * (1.f / 64.f);
        float rs = rsqrtf(var + 1e-5f);
        float o0 = leaky(d0 * rs * gg0 + ee0) + g_h1[(size_t)r * 64 + lane];
        float o1 = leaky(d1 * rs * gg1 + ee1) + g_h1[(size_t)r * 64 + lane + 32];
        g_bufA[(size_t)r * 64 + lane]      = o0;
        g_bufA[(size_t)r * 64 + lane + 32] = o1;
    }
}

// ---------------- final GEMM K=64 + bias + tanh, transpose to [b, n*64+h]
__global__ __launch_bounds__(128) void gemm_final_kernel(
    const float* __restrict__ in, const float* __restrict__ W,
    const float* __restrict__ bias, float* __restrict__ out)
{
    const int lane = threadIdx.x & 31;
    float w0[64], w1[64];
#pragma unroll
    for (int f = 0; f < 64; ++f) { w0[f] = W[f * 64 + lane]; w1[f] = W[f * 64 + lane + 32]; }
    const float bb0 = bias[lane], bb1 = bias[lane + 32];

    int warp = (blockIdx.x * blockDim.x + threadIdx.x) >> 5;
    int nw   = (gridDim.x * blockDim.x) >> 5;
    for (int r = warp; r < MR; r += nw) {
        const float* rp = in + (size_t)r * 64;
        float in0 = rp[lane], in1 = rp[lane + 32];
        float a0 = bb0, a1 = bb1;
#pragma unroll
        for (int f = 0; f < 32; ++f) {
            float v = __shfl_sync(0xffffffffu, in0, f);
            a0 = fmaf(v, w0[f], a0);
            a1 = fmaf(v, w1[f], a1);
        }
#pragma unroll
        for (int f = 0; f < 32; ++f) {
            float v = __shfl_sync(0xffffffffu, in1, f);
            a0 = fmaf(v, w0[32 + f], a0);
            a1 = fmaf(v, w1[32 + f], a1);
        }
        int n = r >> 6, b = r & 63;
        float* op = out + (size_t)b * (NA * HD) + (size_t)n * 64;
        op[lane]      = tanhf(a0);
        op[lane + 32] = tanhf(a1);
    }
}

// ---------------------------------------------------------------------------

extern "C" void kernel_launch(void* const* d_in, const int* in_sizes, int n_in,
                              void* d_out, int out_size)
{
    const float* state = (const float*)d_in[0];
    const int*   ei    = (const int*)d_in[1];
    // d_in[2] batch_size, d_in[3] rej_rate, d_in[4] theta_value: unused
    const float* W1  = (const float*)d_in[5];
    const float* b1  = (const float*)d_in[6];
    const float* W2  = (const float*)d_in[7];
    const float* b2  = (const float*)d_in[8];
    const float* W3  = (const float*)d_in[9];
    const float* b3  = (const float*)d_in[10];
    const float* g1  = (const float*)d_in[11];
    const float* be1 = (const float*)d_in[12];
    const float* g3  = (const float*)d_in[13];
    const float* be3 = (const float*)d_in[14];
    const float* Wf  = (const float*)d_in[15];
    const float* bf  = (const float*)d_in[16];
    float* out = (float*)d_out;

    const int E = in_sizes[1] / 2;

    float *pH1, *pA, *pB, *pX, *pAX;
    cudaGetSymbolAddress((void**)&pH1, g_h1);
    cudaGetSymbolAddress((void**)&pA,  g_bufA);
    cudaGetSymbolAddress((void**)&pB,  g_bufB);
    cudaGetSymbolAddress((void**)&pX,  g_X);
    cudaGetSymbolAddress((void**)&pAX, g_AX);

    // graph preprocessing (CSR by dst, with self loops)
    init_deg_kernel<<<(NA + 255) / 256, 256>>>();
    count_kernel<<<(E + 255) / 256, 256>>>(ei, E);
    dinv_kernel<<<(NA + 255) / 256, 256>>>();
    scan_kernel<<<1, 1024>>>();
    fill_kernel<<<(E + NA + 255) / 256, 256>>>(ei, E);

    // conv1 = (A x) W1 : aggregate first over 16 features
    transpose_kernel<<<(NA * CF + 255) / 256, 256>>>(state);
    agg_kernel<0, CF><<<dim3(NA, 1), 128>>>(pX, pAX, nullptr);
    gemm16_ln_kernel<<<2048, 128>>>(pAX, W1, b1, g1, be1, pH1);

    // conv2: h2 = leaky(A (h1 W2) + b2) + h1
    gemm64_kernel<<<2048, 128>>>(pH1, W2, pA);
    agg_kernel<1, CH><<<dim3(NA, 4), 128>>>(pA, pB, b2);

    // conv3: h3 = leaky(LN(A (h2 W3) + b3)) + h1
    gemm64_kernel<<<2048, 128>>>(pB, W3, pA);
    agg_kernel<2, CH><<<dim3(NA, 4), 128>>>(pA, pB, b3);
    ln_res_kernel<<<2048, 128>>>(g3, be3);

    // out = tanh(h3 Wf + bf), transposed back to [B, N*H]
    gemm_final_kernel<<<2048, 128>>>(pA, Wf, bf, out);
}

// round 3
// speedup vs baseline: 1.1358x; 1.1358x over previous
#include <cuda_runtime.h>
#include <cuda_fp16.h>
#include <math.h>

// ---------------------------------------------------------------------------
// GNN_Encoder: 3x GCNConv (self-loops, sym-norm) + LN/leaky/residual + tanh
// B=64, N=10000, F=16, H=64, E=320000
// R2: fp16 pre-aggregation operands (halve L2 traffic of the SpMMs),
//     LN fused into agg3 epilogue, 1-pass scan, half2-coalesced GEMM stores.
// ---------------------------------------------------------------------------

namespace {
constexpr int NA = 10000;
constexpr int NF = 16;
constexpr int HD = 64;
constexpr int BT = 64;
constexpr int MR = NA * BT;        // 640000 rows
constexpr int CH = BT * HD;        // 4096 hidden cols per node-row
constexpr int CF = BT * NF;        // 1024 input cols per node-row
constexpr int EMAX = 330000;
}

// scratch (device globals; no allocation allowed)
__device__ __align__(256) float  g_h1[MR * HD];       // h1 (fp32)
__device__ __align__(256) float  g_bufA[MR * HD];     // h3 (fp32)
__device__ __align__(256) float  g_bufB[MR * HD];     // h2 (fp32)
__device__ __align__(256) __half g_hHalf[MR * HD];    // fp16 pre-agg operand
__device__ __align__(256) __half g_X[NA * CF];        // fp16 pre-scaled input
__device__ __align__(256) float  g_AX[NA * CF];       // A·x (fp32)
__device__ int   g_deg[NA];
__device__ float g_dinv[NA];
__device__ int   g_rowptr[NA + 1];
__device__ int   g_fillptr[NA];
__device__ int   g_col[EMAX];

__device__ __forceinline__ float warp_sum(float v) {
#pragma unroll
    for (int off = 16; off > 0; off >>= 1)
        v += __shfl_xor_sync(0xffffffffu, v, off);
    return v;
}

__device__ __forceinline__ float leaky(float x) {
    return x >= 0.f ? x : 0.01f * x;
}

// ---------------- graph preprocessing ----------------

__global__ void init_deg_kernel() {
    int i = blockIdx.x * blockDim.x + threadIdx.x;
    if (i < NA) g_deg[i] = 1;   // self loop
}

__global__ void count_kernel(const int* __restrict__ ei, int E) {
    int i = blockIdx.x * blockDim.x + threadIdx.x;
    if (i < E) atomicAdd(&g_deg[ei[E + i]], 1);   // dst row
}

__global__ void dinv_kernel() {
    int i = blockIdx.x * blockDim.x + threadIdx.x;
    if (i < NA) g_dinv[i] = rsqrtf((float)g_deg[i]);
}

// one-pass scan: 1024 threads x 10 items, warp-shfl hierarchy
__global__ __launch_bounds__(1024) void scan_kernel() {
    __shared__ int warp_tot[32];
    const int tid  = threadIdx.x;
    const int lane = tid & 31;
    const int wid  = tid >> 5;
    const int base = tid * 10;

    int v[10];
    int run = 0;
#pragma unroll
    for (int k = 0; k < 10; ++k) {
        int i = base + k;
        int x = (i < NA) ? g_deg[i] : 0;
        run += x;
        v[k] = run;                    // inclusive within thread
    }
    // warp inclusive scan of thread totals
    int s = run;
#pragma unroll
    for (int off = 1; off < 32; off <<= 1) {
        int y = __shfl_up_sync(0xffffffffu, s, off);
        if (lane >= off) s += y;
    }
    if (lane == 31) warp_tot[wid] = s;
    __syncthreads();
    if (wid == 0) {
        int w = warp_tot[lane];
#pragma unroll
        for (int off = 1; off < 32; off <<= 1) {
            int y = __shfl_up_sync(0xffffffffu, w, off);
            if (lane >= off) w += y;
        }
        warp_tot[lane] = w;            // inclusive warp prefix
    }
    __syncthreads();
    const int warp_off = (wid == 0) ? 0 : warp_tot[wid - 1];
    const int excl = warp_off + (s - run);   // exclusive offset of this thread
    if (tid == 0) g_rowptr[0] = 0;
#pragma unroll
    for (int k = 0; k < 10; ++k) {
        int i = base + k;
        if (i < NA) {
            g_rowptr[i + 1] = excl + v[k];
            g_fillptr[i]    = excl + (k ? v[k - 1] : 0);
        }
    }
}

__global__ void fill_kernel(const int* __restrict__ ei, int E) {
    int i = blockIdx.x * blockDim.x + threadIdx.x;
    if (i < E) {
        int d = ei[E + i];
        int pos = atomicAdd(&g_fillptr[d], 1);
        g_col[pos] = ei[i];
    } else if (i < E + NA) {
        int n = i - E;
        int pos = atomicAdd(&g_fillptr[n], 1);
        g_col[pos] = n;
    }
}

// ---------------- transpose + pre-scale: state[b, n*16+f] -> X[n][b][f]*dinv[n] (fp16)
__global__ void transpose_kernel(const float* __restrict__ state) {
    int i = blockIdx.x * blockDim.x + threadIdx.x;
    if (i < NA * CF) {
        int f = i & 15;
        int b = (i >> 4) & 63;
        int n = i >> 10;
        g_X[i] = __float2half(state[(size_t)b * (NA * NF) + n * NF + f] * g_dinv[n]);
    }
}

// ---------------- conv1 aggregation: AX[d] = dinv[d] * sum_s X[s]  (1024 fp16 cols)
__global__ __launch_bounds__(128) void agg16_kernel(
    const __half* __restrict__ src, float* __restrict__ dst)
{
    const int d = blockIdx.x;
    const int c = threadIdx.x * 8;   // 8 halves per thread
    float acc[8];
#pragma unroll
    for (int k = 0; k < 8; ++k) acc[k] = 0.f;

    const int beg = g_rowptr[d], end = g_rowptr[d + 1];
#pragma unroll 4
    for (int j = beg; j < end; ++j) {
        const int s = g_col[j];
        float4 u = *reinterpret_cast<const float4*>(src + (size_t)s * CF + c);
        const __half2* h = reinterpret_cast<const __half2*>(&u);
#pragma unroll
        for (int k = 0; k < 4; ++k) {
            float2 f = __half22float2(h[k]);
            acc[2 * k]     += f.x;
            acc[2 * k + 1] += f.y;
        }
    }
    const float sc = g_dinv[d];
    float* op = dst + (size_t)d * CF + c;
#pragma unroll
    for (int k = 0; k < 8; ++k) op[k] = acc[k] * sc;
}

// ---------------- hidden aggregation (4096 cols fp16, 2 chunks of 2048)
// MODE 1: +b2, leaky, +h1 residual  -> h2 (fp32)
// MODE 2: +b3, LayerNorm(g3,be3), leaky, +h1 residual -> h3 (fp32)
template <int MODE>
__global__ __launch_bounds__(128) void aggH_kernel(
    const __half* __restrict__ src, float* __restrict__ dst,
    const float* __restrict__ bias,
    const float* __restrict__ gma, const float* __restrict__ bta)
{
    const int d  = blockIdx.x;
    const int c0 = blockIdx.y * 2048 + threadIdx.x * 16;  // 16 halves per thread
    const int f0 = c0 & 63;

    float acc[16];
#pragma unroll
    for (int k = 0; k < 16; ++k) acc[k] = 0.f;

    const int beg = g_rowptr[d], end = g_rowptr[d + 1];
#pragma unroll 2
    for (int j = beg; j < end; ++j) {
        const int s = g_col[j];
        const __half* row = src + (size_t)s * CH + c0;
        float4 u0 = *reinterpret_cast<const float4*>(row);
        float4 u1 = *reinterpret_cast<const float4*>(row + 8);
        const __half2* h0 = reinterpret_cast<const __half2*>(&u0);
        const __half2* h1 = reinterpret_cast<const __half2*>(&u1);
#pragma unroll
        for (int k = 0; k < 4; ++k) {
            float2 a = __half22float2(h0[k]);
            float2 b = __half22float2(h1[k]);
            acc[2 * k]      += a.x;
            acc[2 * k + 1]  += a.y;
            acc[8 + 2 * k]     += b.x;
            acc[8 + 2 * k + 1] += b.y;
        }
    }

    const float sc = g_dinv[d];
    float v[16];
#pragma unroll
    for (int k = 0; k < 16; ++k) v[k] = fmaf(acc[k], sc, bias[f0 + k]);

    const float* h1row = g_h1 + (size_t)d * CH + c0;
    float out[16];

    if (MODE == 1) {
#pragma unroll
        for (int k = 0; k < 16; ++k) out[k] = leaky(v[k]) + h1row[k];
    } else {
        // LayerNorm over 64 feats = group of 4 consecutive threads
        float s1 = 0.f, s2 = 0.f;
#pragma unroll
        for (int k = 0; k < 16; ++k) { s1 += v[k]; s2 += v[k] * v[k]; }
        s1 += __shfl_xor_sync(0xffffffffu, s1, 1);
        s2 += __shfl_xor_sync(0xffffffffu, s2, 1);
        s1 += __shfl_xor_sync(0xffffffffu, s1, 2);
        s2 += __shfl_xor_sync(0xffffffffu, s2, 2);
        const float mean = s1 * (1.f / 64.f);
        const float var  = fmaf(s2, 1.f / 64.f, -mean * mean);
        const float rs   = rsqrtf(var + 1e-5f);
#pragma unroll
        for (int k = 0; k < 16; ++k)
            out[k] = leaky(fmaf((v[k] - mean) * rs, gma[f0 + k], bta[f0 + k])) + h1row[k];
    }

    float* op = dst + (size_t)d * CH + c0;
#pragma unroll
    for (int k = 0; k < 16; k += 4)
        *reinterpret_cast<float4*>(op + k) =
            make_float4(out[k], out[k + 1], out[k + 2], out[k + 3]);
}

// ---------------- GEMM K=16 + bias + LayerNorm + leaky -> h1 (fp32)
__global__ __launch_bounds__(128) void gemm16_ln_kernel(
    const float* __restrict__ in, const float* __restrict__ W,
    const float* __restrict__ bias, const float* __restrict__ gma,
    const float* __restrict__ bta, float* __restrict__ out)
{
    const int lane = threadIdx.x & 31;
    float w0[16], w1[16];
#pragma unroll
    for (int f = 0; f < 16; ++f) { w0[f] = W[f * 64 + lane]; w1[f] = W[f * 64 + lane + 32]; }
    const float bb0 = bias[lane], bb1 = bias[lane + 32];
    const float gg0 = gma[lane],  gg1 = gma[lane + 32];
    const float ee0 = bta[lane],  ee1 = bta[lane + 32];

    int warp = (blockIdx.x * blockDim.x + threadIdx.x) >> 5;
    int nw   = (gridDim.x * blockDim.x) >> 5;
    for (int r = warp; r < MR; r += nw) {
        float iv = (lane < 16) ? in[(size_t)r * 16 + lane] : 0.f;
        float a0 = bb0, a1 = bb1;
#pragma unroll
        for (int f = 0; f < 16; ++f) {
            float v = __shfl_sync(0xffffffffu, iv, f);
            a0 = fmaf(v, w0[f], a0);
            a1 = fmaf(v, w1[f], a1);
        }
        float mean = warp_sum(a0 + a1) * (1.f / 64.f);
        float d0 = a0 - mean, d1 = a1 - mean;
        float var = warp_sum(d0 * d0 + d1 * d1) * (1.f / 64.f);
        float rs = rsqrtf(var + 1e-5f);
        out[(size_t)r * 64 + lane]      = leaky(d0 * rs * gg0 + ee0);
        out[(size_t)r * 64 + lane + 32] = leaky(d1 * rs * gg1 + ee1);
    }
}

// ---------------- GEMM K=64, epilogue * dinv[node], fp16 output (half2 stores)
__global__ __launch_bounds__(128) void gemm64_half_kernel(
    const float* __restrict__ in, const float* __restrict__ W,
    __half* __restrict__ out)
{
    const int lane = threadIdx.x & 31;
    const int n0 = 2 * lane, n1 = 2 * lane + 1;
    float w0[64], w1[64];
#pragma unroll
    for (int f = 0; f < 64; ++f) { w0[f] = W[f * 64 + n0]; w1[f] = W[f * 64 + n1]; }

    int warp = (blockIdx.x * blockDim.x + threadIdx.x) >> 5;
    int nw   = (gridDim.x * blockDim.x) >> 5;
    for (int r = warp; r < MR; r += nw) {
        const float* rp = in + (size_t)r * 64;
        float in0 = rp[lane], in1 = rp[lane + 32];
        float a0 = 0.f, a1 = 0.f;
#pragma unroll
        for (int f = 0; f < 32; ++f) {
            float v = __shfl_sync(0xffffffffu, in0, f);
            a0 = fmaf(v, w0[f], a0);
            a1 = fmaf(v, w1[f], a1);
        }
#pragma unroll
        for (int f = 0; f < 32; ++f) {
            float v = __shfl_sync(0xffffffffu, in1, f);
            a0 = fmaf(v, w0[32 + f], a0);
            a1 = fmaf(v, w1[32 + f], a1);
        }
        const float s = g_dinv[r >> 6];
        reinterpret_cast<__half2*>(out + (size_t)r * 64)[lane] =
            __floats2half2_rn(a0 * s, a1 * s);
    }
}

// ---------------- final GEMM K=64 + bias + tanh, transpose to [b, n*64+h]
__global__ __launch_bounds__(128) void gemm_final_kernel(
    const float* __restrict__ in, const float* __restrict__ W,
    const float* __restrict__ bias, float* __restrict__ out)
{
    const int lane = threadIdx.x & 31;
    const int n0 = 2 * lane, n1 = 2 * lane + 1;
    float w0[64], w1[64];
#pragma unroll
    for (int f = 0; f < 64; ++f) { w0[f] = W[f * 64 + n0]; w1[f] = W[f * 64 + n1]; }
    const float bb0 = bias[n0], bb1 = bias[n1];

    int warp = (blockIdx.x * blockDim.x + threadIdx.x) >> 5;
    int nw   = (gridDim.x * blockDim.x) >> 5;
    for (int r = warp; r < MR; r += nw) {
        const float* rp = in + (size_t)r * 64;
        float in0 = rp[lane], in1 = rp[lane + 32];
        float a0 = bb0, a1 = bb1;
#pragma unroll
        for (int f = 0; f < 32; ++f) {
            float v = __shfl_sync(0xffffffffu, in0, f);
            a0 = fmaf(v, w0[f], a0);
            a1 = fmaf(v, w1[f], a1);
        }
#pragma unroll
        for (int f = 0; f < 32; ++f) {
            float v = __shfl_sync(0xffffffffu, in1, f);
            a0 = fmaf(v, w1 == w1 ? w0[32 + f] : 0.f, a0);  // keep simple: w0
            a1 = fmaf(v, w1[32 + f], a1);
        }
        int n = r >> 6, b = r & 63;
        reinterpret_cast<float2*>(out + (size_t)b * (NA * HD) + (size_t)n * 64)[lane] =
            make_float2(tanhf(a0), tanhf(a1));
    }
}

// ---------------------------------------------------------------------------

extern "C" void kernel_launch(void* const* d_in, const int* in_sizes, int n_in,
                              void* d_out, int out_size)
{
    const float* state = (const float*)d_in[0];
    const int*   ei    = (const int*)d_in[1];
    const float* W1  = (const float*)d_in[5];
    const float* b1  = (const float*)d_in[6];
    const float* W2  = (const float*)d_in[7];
    const float* b2  = (const float*)d_in[8];
    const float* W3  = (const float*)d_in[9];
    const float* b3  = (const float*)d_in[10];
    const float* g1  = (const float*)d_in[11];
    const float* be1 = (const float*)d_in[12];
    const float* g3  = (const float*)d_in[13];
    const float* be3 = (const float*)d_in[14];
    const float* Wf  = (const float*)d_in[15];
    const float* bf  = (const float*)d_in[16];
    float* out = (float*)d_out;

    const int E = in_sizes[1] / 2;

    float *pH1, *pA, *pB, *pAX;
    __half *pHH, *pX;
    cudaGetSymbolAddress((void**)&pH1, g_h1);
    cudaGetSymbolAddress((void**)&pA,  g_bufA);
    cudaGetSymbolAddress((void**)&pB,  g_bufB);
    cudaGetSymbolAddress((void**)&pAX, g_AX);
    cudaGetSymbolAddress((void**)&pHH, g_hHalf);
    cudaGetSymbolAddress((void**)&pX,  g_X);

    // graph preprocessing (CSR by dst, with self loops)
    init_deg_kernel<<<(NA + 255) / 256, 256>>>();
    count_kernel<<<(E + 255) / 256, 256>>>(ei, E);
    dinv_kernel<<<(NA + 255) / 256, 256>>>();
    scan_kernel<<<1, 1024>>>();
    fill_kernel<<<(E + NA + 255) / 256, 256>>>(ei, E);

    // conv1 = (A x) W1: aggregate 16-feature input first (fp16 operand)
    transpose_kernel<<<(NA * CF + 255) / 256, 256>>>(state);
    agg16_kernel<<<NA, 128>>>(pX, pAX);
    gemm16_ln_kernel<<<2048, 128>>>(pAX, W1, b1, g1, be1, pH1);

    // conv2: h2 = leaky(A (h1 W2) + b2) + h1
    gemm64_half_kernel<<<2048, 128>>>(pH1, W2, pHH);
    aggH_kernel<1><<<dim3(NA, 2), 128>>>(pHH, pB, b2, nullptr, nullptr);

    // conv3: h3 = leaky(LN(A (h2 W3) + b3)) + h1   (LN fused into agg epilogue)
    gemm64_half_kernel<<<2048, 128>>>(pB, W3, pHH);
    aggH_kernel<2><<<dim3(NA, 2), 128>>>(pHH, pA, b3, g3, be3);

    // out = tanh(h3 Wf + bf), transposed back to [B, N*H]
    gemm_final_kernel<<<2048, 128>>>(pA, Wf, bf, out);
}

// round 7
// speedup vs baseline: 2.4119x; 2.1235x over previous
#include <cuda_runtime.h>
#include <cuda_fp16.h>
#include <stdint.h>
#include <math.h>

// ---------------------------------------------------------------------------
// GNN_Encoder: 3x GCNConv (self-loops, sym-norm) + LN/leaky/residual + tanh
// B=64, N=10000, F=16, H=64, E=320000
// R7 (= R6 with the W1 transpose-index typo fixed): HMMA (mma.sync m16n8k16
//     f16->f32) for all GEMMs, fp16 inter-stage buffers, fused epilogues
//     (dinv / bias+LN+leaky / bias+tanh+transpose).
// ---------------------------------------------------------------------------

namespace {
constexpr int NA = 10000;
constexpr int NF = 16;
constexpr int HD = 64;
constexpr int BT = 64;
constexpr int MR = NA * BT;        // 640000 rows ([node][batch] major)
constexpr int CH = BT * HD;        // 4096 hidden cols per node
constexpr int CF = BT * NF;        // 1024 input cols per node
constexpr int EMAX = 330000;
constexpr int NTILES = MR / 16;    // 40000 16-row mma tiles
}

// scratch (device globals; no allocation allowed)
__device__ __align__(256) float  g_h1[MR * HD];       // h1 fp32 (residuals)
__device__ __align__(256) __half g_h1h[MR * HD];      // h1 fp16 (gemm input)
__device__ __align__(256) __half g_h2h[MR * HD];      // h2 fp16
__device__ __align__(256) __half g_h3h[MR * HD];      // h3 fp16
__device__ __align__(256) __half g_pre[MR * HD];      // pre-agg operand fp16
__device__ __align__(256) __half g_X[NA * CF];        // pre-scaled input fp16
__device__ __align__(256) __half g_AX[NA * CF];       // A·x fp16
__device__ __half g_W1t[HD * NF];   // [n][k] transposed fp16 weights
__device__ __half g_W2t[HD * HD];
__device__ __half g_W3t[HD * HD];
__device__ __half g_Wft[HD * HD];
__device__ int   g_deg[NA];
__device__ float g_dinv[NA];
__device__ int   g_rowptr[NA + 1];
__device__ int   g_fillptr[NA];
__device__ int   g_col[EMAX];

__device__ __forceinline__ float leaky(float x) {
    return x >= 0.f ? x : 0.01f * x;
}

__device__ __forceinline__ void mma16816(float c[4],
    uint32_t a0, uint32_t a1, uint32_t a2, uint32_t a3,
    uint32_t b0, uint32_t b1)
{
    asm volatile(
        "mma.sync.aligned.m16n8k16.row.col.f32.f16.f16.f32 "
        "{%0,%1,%2,%3},{%4,%5,%6,%7},{%8,%9},{%0,%1,%2,%3};"
        : "+f"(c[0]), "+f"(c[1]), "+f"(c[2]), "+f"(c[3])
        : "r"(a0), "r"(a1), "r"(a2), "r"(a3), "r"(b0), "r"(b1));
}

// ---------------- graph preprocessing ----------------

__global__ void init_deg_kernel() {
    int i = blockIdx.x * blockDim.x + threadIdx.x;
    if (i < NA) g_deg[i] = 1;
}

__global__ void count_kernel(const int* __restrict__ ei, int E) {
    int i = blockIdx.x * blockDim.x + threadIdx.x;
    if (i < E) atomicAdd(&g_deg[ei[E + i]], 1);
}

__global__ void dinv_kernel() {
    int i = blockIdx.x * blockDim.x + threadIdx.x;
    if (i < NA) g_dinv[i] = rsqrtf((float)g_deg[i]);
}

__global__ __launch_bounds__(1024) void scan_kernel() {
    __shared__ int warp_tot[32];
    const int tid  = threadIdx.x;
    const int lane = tid & 31;
    const int wid  = tid >> 5;
    const int base = tid * 10;

    int v[10];
    int run = 0;
#pragma unroll
    for (int k = 0; k < 10; ++k) {
        int i = base + k;
        int x = (i < NA) ? g_deg[i] : 0;
        run += x;
        v[k] = run;
    }
    int s = run;
#pragma unroll
    for (int off = 1; off < 32; off <<= 1) {
        int y = __shfl_up_sync(0xffffffffu, s, off);
        if (lane >= off) s += y;
    }
    if (lane == 31) warp_tot[wid] = s;
    __syncthreads();
    if (wid == 0) {
        int w = warp_tot[lane];
#pragma unroll
        for (int off = 1; off < 32; off <<= 1) {
            int y = __shfl_up_sync(0xffffffffu, w, off);
            if (lane >= off) w += y;
        }
        warp_tot[lane] = w;
    }
    __syncthreads();
    const int warp_off = (wid == 0) ? 0 : warp_tot[wid - 1];
    const int excl = warp_off + (s - run);
    if (tid == 0) g_rowptr[0] = 0;
#pragma unroll
    for (int k = 0; k < 10; ++k) {
        int i = base + k;
        if (i < NA) {
            g_rowptr[i + 1] = excl + v[k];
            g_fillptr[i]    = excl + (k ? v[k - 1] : 0);
        }
    }
}

__global__ void fill_kernel(const int* __restrict__ ei, int E) {
    int i = blockIdx.x * blockDim.x + threadIdx.x;
    if (i < E) {
        int d = ei[E + i];
        int pos = atomicAdd(&g_fillptr[d], 1);
        g_col[pos] = ei[i];
    } else if (i < E + NA) {
        int n = i - E;
        int pos = atomicAdd(&g_fillptr[n], 1);
        g_col[pos] = n;
    }
}

// ---------------- weight prep: fp16 transposed [n][k]
__global__ void prep_w_kernel(const float* __restrict__ W1,
                              const float* __restrict__ W2,
                              const float* __restrict__ W3,
                              const float* __restrict__ Wf)
{
    int i = blockIdx.x * blockDim.x + threadIdx.x;
    if (i < HD * HD) {
        int n = i / HD, k = i % HD;
        g_W2t[i] = __float2half(W2[k * HD + n]);
        g_W3t[i] = __float2half(W3[k * HD + n]);
        g_Wft[i] = __float2half(Wf[k * HD + n]);
    }
    if (i < HD * NF) {
        int n = i / NF, k = i % NF;
        g_W1t[i] = __float2half(W1[k * HD + n]);
    }
}

// ---------------- transpose + pre-scale: state[b, n*16+f] -> X[n][b][f]*dinv[n]
__global__ void transpose_kernel(const float* __restrict__ state) {
    int i = blockIdx.x * blockDim.x + threadIdx.x;
    if (i < NA * CF) {
        int f = i & 15;
        int b = (i >> 4) & 63;
        int n = i >> 10;
        g_X[i] = __float2half(state[(size_t)b * (NA * NF) + n * NF + f] * g_dinv[n]);
    }
}

// ---------------- conv1 aggregation: AX[d] = dinv[d] * sum_s X[s] (fp16 out)
__global__ __launch_bounds__(128) void agg16_kernel(
    const __half* __restrict__ src, __half* __restrict__ dst)
{
    const int d = blockIdx.x;
    const int c = threadIdx.x * 8;
    float acc[8];
#pragma unroll
    for (int k = 0; k < 8; ++k) acc[k] = 0.f;

    const int beg = g_rowptr[d], end = g_rowptr[d + 1];
#pragma unroll 4
    for (int j = beg; j < end; ++j) {
        const int s = g_col[j];
        float4 u = *reinterpret_cast<const float4*>(src + (size_t)s * CF + c);
        const __half2* h = reinterpret_cast<const __half2*>(&u);
#pragma unroll
        for (int k = 0; k < 4; ++k) {
            float2 f = __half22float2(h[k]);
            acc[2 * k]     += f.x;
            acc[2 * k + 1] += f.y;
        }
    }
    const float sc = g_dinv[d];
    __half2 o[4];
#pragma unroll
    for (int k = 0; k < 4; ++k)
        o[k] = __floats2half2_rn(acc[2 * k] * sc, acc[2 * k + 1] * sc);
    *reinterpret_cast<float4*>(dst + (size_t)d * CF + c) =
        *reinterpret_cast<const float4*>(o);
}

// ---------------- hidden aggregation (4096 fp16 cols, 2 chunks of 2048)
// MODE 1: +b2, leaky, +h1 -> h2 fp16
// MODE 2: +b3, LN(g3,be3), leaky, +h1 -> h3 fp16
template <int MODE>
__global__ __launch_bounds__(128) void aggH_kernel(
    const __half* __restrict__ src, __half* __restrict__ dst,
    const float* __restrict__ bias,
    const float* __restrict__ gma, const float* __restrict__ bta)
{
    const int d  = blockIdx.x;
    const int c0 = blockIdx.y * 2048 + threadIdx.x * 16;
    const int f0 = c0 & 63;

    float acc[16];
#pragma unroll
    for (int k = 0; k < 16; ++k) acc[k] = 0.f;

    const int beg = g_rowptr[d], end = g_rowptr[d + 1];
#pragma unroll 2
    for (int j = beg; j < end; ++j) {
        const int s = g_col[j];
        const __half* row = src + (size_t)s * CH + c0;
        float4 u0 = *reinterpret_cast<const float4*>(row);
        float4 u1 = *reinterpret_cast<const float4*>(row + 8);
        const __half2* h0 = reinterpret_cast<const __half2*>(&u0);
        const __half2* h1 = reinterpret_cast<const __half2*>(&u1);
#pragma unroll
        for (int k = 0; k < 4; ++k) {
            float2 a = __half22float2(h0[k]);
            float2 b = __half22float2(h1[k]);
            acc[2 * k]         += a.x;
            acc[2 * k + 1]     += a.y;
            acc[8 + 2 * k]     += b.x;
            acc[8 + 2 * k + 1] += b.y;
        }
    }

    const float sc = g_dinv[d];
    float v[16];
#pragma unroll
    for (int k = 0; k < 16; ++k) v[k] = fmaf(acc[k], sc, bias[f0 + k]);

    const float* h1row = g_h1 + (size_t)d * CH + c0;
    float out[16];

    if (MODE == 1) {
#pragma unroll
        for (int k = 0; k < 16; ++k) out[k] = leaky(v[k]) + h1row[k];
    } else {
        float s1 = 0.f, s2 = 0.f;
#pragma unroll
        for (int k = 0; k < 16; ++k) { s1 += v[k]; s2 += v[k] * v[k]; }
        s1 += __shfl_xor_sync(0xffffffffu, s1, 1);
        s2 += __shfl_xor_sync(0xffffffffu, s2, 1);
        s1 += __shfl_xor_sync(0xffffffffu, s1, 2);
        s2 += __shfl_xor_sync(0xffffffffu, s2, 2);
        const float mean = s1 * (1.f / 64.f);
        const float var  = fmaf(s2, 1.f / 64.f, -mean * mean);
        const float rs   = rsqrtf(var + 1e-5f);
#pragma unroll
        for (int k = 0; k < 16; ++k)
            out[k] = leaky(fmaf((v[k] - mean) * rs, gma[f0 + k], bta[f0 + k])) + h1row[k];
    }

    __half2 o[8];
#pragma unroll
    for (int k = 0; k < 8; ++k)
        o[k] = __floats2half2_rn(out[2 * k], out[2 * k + 1]);
    float4* op = reinterpret_cast<float4*>(dst + (size_t)d * CH + c0);
    op[0] = reinterpret_cast<const float4*>(o)[0];
    op[1] = reinterpret_cast<const float4*>(o)[1];
}

// ---------------- HMMA GEMM K=16 + bias + LN + leaky -> h1 fp32 + fp16
__global__ __launch_bounds__(128) void hgemm16_ln_kernel(
    const __half* __restrict__ in, const float* __restrict__ bias,
    const float* __restrict__ gma, const float* __restrict__ bta,
    float* __restrict__ out32, __half* __restrict__ out16)
{
    const int lane = threadIdx.x & 31;
    const int g = lane >> 2, t = lane & 3;

    // B frags (K=16: one k-step), col n = nt*8+g, k = t*2 (+8)
    uint32_t B0[8], B1[8];
    const uint32_t* wp = reinterpret_cast<const uint32_t*>(g_W1t);
#pragma unroll
    for (int nt = 0; nt < 8; ++nt) {
        B0[nt] = wp[((nt * 8 + g) * 16 + t * 2) >> 1];
        B1[nt] = wp[((nt * 8 + g) * 16 + 8 + t * 2) >> 1];
    }
    // per-lane epilogue params, cols nt*8 + t*2 + {0,1}
    float2 bv[8], gv[8], ev[8];
#pragma unroll
    for (int nt = 0; nt < 8; ++nt) {
        bv[nt] = *reinterpret_cast<const float2*>(bias + nt * 8 + t * 2);
        gv[nt] = *reinterpret_cast<const float2*>(gma  + nt * 8 + t * 2);
        ev[nt] = *reinterpret_cast<const float2*>(bta  + nt * 8 + t * 2);
    }

    const int warp = (blockIdx.x * blockDim.x + threadIdx.x) >> 5;
    const int nw   = (gridDim.x * blockDim.x) >> 5;
    for (int tile = warp; tile < NTILES; tile += nw) {
        const int rb = tile * 16;
        const uint32_t* ap = reinterpret_cast<const uint32_t*>(in + (size_t)rb * 16);
        uint32_t a0 = ap[(g * 16 + t * 2) >> 1];
        uint32_t a1 = ap[((g + 8) * 16 + t * 2) >> 1];
        uint32_t a2 = ap[(g * 16 + 8 + t * 2) >> 1];
        uint32_t a3 = ap[((g + 8) * 16 + 8 + t * 2) >> 1];

        float C[8][4];
#pragma unroll
        for (int nt = 0; nt < 8; ++nt) { C[nt][0] = C[nt][1] = C[nt][2] = C[nt][3] = 0.f; }
#pragma unroll
        for (int nt = 0; nt < 8; ++nt)
            mma16816(C[nt], a0, a1, a2, a3, B0[nt], B1[nt]);

        // + bias
        float va[16], vb[16];   // row g (a), row g+8 (b); 2 vals per nt
#pragma unroll
        for (int nt = 0; nt < 8; ++nt) {
            va[2 * nt]     = C[nt][0] + bv[nt].x;
            va[2 * nt + 1] = C[nt][1] + bv[nt].y;
            vb[2 * nt]     = C[nt][2] + bv[nt].x;
            vb[2 * nt + 1] = C[nt][3] + bv[nt].y;
        }
        // LN per row across the 4 lanes of this row group
        float s1a = 0.f, s2a = 0.f, s1b = 0.f, s2b = 0.f;
#pragma unroll
        for (int k = 0; k < 16; ++k) {
            s1a += va[k]; s2a += va[k] * va[k];
            s1b += vb[k]; s2b += vb[k] * vb[k];
        }
#pragma unroll
        for (int off = 1; off <= 2; off <<= 1) {
            s1a += __shfl_xor_sync(0xffffffffu, s1a, off);
            s2a += __shfl_xor_sync(0xffffffffu, s2a, off);
            s1b += __shfl_xor_sync(0xffffffffu, s1b, off);
            s2b += __shfl_xor_sync(0xffffffffu, s2b, off);
        }
        const float ma = s1a * (1.f / 64.f);
        const float ra = rsqrtf(fmaf(s2a, 1.f / 64.f, -ma * ma) + 1e-5f);
        const float mb = s1b * (1.f / 64.f);
        const float rbv = rsqrtf(fmaf(s2b, 1.f / 64.f, -mb * mb) + 1e-5f);

        float* oa32 = out32 + (size_t)(rb + g) * 64 + t * 2;
        float* ob32 = out32 + (size_t)(rb + g + 8) * 64 + t * 2;
        __half* oa16 = out16 + (size_t)(rb + g) * 64 + t * 2;
        __half* ob16 = out16 + (size_t)(rb + g + 8) * 64 + t * 2;
#pragma unroll
        for (int nt = 0; nt < 8; ++nt) {
            float x0 = leaky(fmaf((va[2 * nt]     - ma) * ra, gv[nt].x, ev[nt].x));
            float x1 = leaky(fmaf((va[2 * nt + 1] - ma) * ra, gv[nt].y, ev[nt].y));
            float y0 = leaky(fmaf((vb[2 * nt]     - mb) * rbv, gv[nt].x, ev[nt].x));
            float y1 = leaky(fmaf((vb[2 * nt + 1] - mb) * rbv, gv[nt].y, ev[nt].y));
            *reinterpret_cast<float2*>(oa32 + nt * 8) = make_float2(x0, x1);
            *reinterpret_cast<float2*>(ob32 + nt * 8) = make_float2(y0, y1);
            *reinterpret_cast<__half2*>(oa16 + nt * 8) = __floats2half2_rn(x0, x1);
            *reinterpret_cast<__half2*>(ob16 + nt * 8) = __floats2half2_rn(y0, y1);
        }
    }
}

// ---------------- HMMA GEMM K=64, epilogue * dinv[node] -> fp16
__global__ __launch_bounds__(128) void hgemm64_kernel(
    const __half* __restrict__ in, const __half* __restrict__ Wt,
    __half* __restrict__ out)
{
    const int lane = threadIdx.x & 31;
    const int g = lane >> 2, t = lane & 3;

    uint32_t B0[4][8], B1[4][8];
    const uint32_t* wp = reinterpret_cast<const uint32_t*>(Wt);
#pragma unroll
    for (int kk = 0; kk < 4; ++kk)
#pragma unroll
        for (int nt = 0; nt < 8; ++nt) {
            B0[kk][nt] = wp[((nt * 8 + g) * 64 + kk * 16 + t * 2) >> 1];
            B1[kk][nt] = wp[((nt * 8 + g) * 64 + kk * 16 + 8 + t * 2) >> 1];
        }

    const int warp = (blockIdx.x * blockDim.x + threadIdx.x) >> 5;
    const int nw   = (gridDim.x * blockDim.x) >> 5;
    for (int tile = warp; tile < NTILES; tile += nw) {
        const int rb = tile * 16;
        const uint32_t* ap = reinterpret_cast<const uint32_t*>(in + (size_t)rb * 64);

        float C[8][4];
#pragma unroll
        for (int nt = 0; nt < 8; ++nt) { C[nt][0] = C[nt][1] = C[nt][2] = C[nt][3] = 0.f; }
#pragma unroll
        for (int kk = 0; kk < 4; ++kk) {
            uint32_t a0 = ap[(g * 64 + kk * 16 + t * 2) >> 1];
            uint32_t a1 = ap[((g + 8) * 64 + kk * 16 + t * 2) >> 1];
            uint32_t a2 = ap[(g * 64 + kk * 16 + 8 + t * 2) >> 1];
            uint32_t a3 = ap[((g + 8) * 64 + kk * 16 + 8 + t * 2) >> 1];
#pragma unroll
            for (int nt = 0; nt < 8; ++nt)
                mma16816(C[nt], a0, a1, a2, a3, B0[kk][nt], B1[kk][nt]);
        }

        const float s = g_dinv[rb >> 6];
        __half* oa = out + (size_t)(rb + g) * 64 + t * 2;
        __half* ob = out + (size_t)(rb + g + 8) * 64 + t * 2;
#pragma unroll
        for (int nt = 0; nt < 8; ++nt) {
            *reinterpret_cast<__half2*>(oa + nt * 8) =
                __floats2half2_rn(C[nt][0] * s, C[nt][1] * s);
            *reinterpret_cast<__half2*>(ob + nt * 8) =
                __floats2half2_rn(C[nt][2] * s, C[nt][3] * s);
        }
    }
}

// ---------------- HMMA final GEMM K=64 + bias + tanh, transposed store
__global__ __launch_bounds__(128) void hgemm_final_kernel(
    const __half* __restrict__ in, const float* __restrict__ bias,
    float* __restrict__ out)
{
    const int lane = threadIdx.x & 31;
    const int g = lane >> 2, t = lane & 3;

    uint32_t B0[4][8], B1[4][8];
    const uint32_t* wp = reinterpret_cast<const uint32_t*>(g_Wft);
#pragma unroll
    for (int kk = 0; kk < 4; ++kk)
#pragma unroll
        for (int nt = 0; nt < 8; ++nt) {
            B0[kk][nt] = wp[((nt * 8 + g) * 64 + kk * 16 + t * 2) >> 1];
            B1[kk][nt] = wp[((nt * 8 + g) * 64 + kk * 16 + 8 + t * 2) >> 1];
        }
    float2 bv[8];
#pragma unroll
    for (int nt = 0; nt < 8; ++nt)
        bv[nt] = *reinterpret_cast<const float2*>(bias + nt * 8 + t * 2);

    const int warp = (blockIdx.x * blockDim.x + threadIdx.x) >> 5;
    const int nw   = (gridDim.x * blockDim.x) >> 5;
    for (int tile = warp; tile < NTILES; tile += nw) {
        const int rb = tile * 16;
        const uint32_t* ap = reinterpret_cast<const uint32_t*>(in + (size_t)rb * 64);

        float C[8][4];
#pragma unroll
        for (int nt = 0; nt < 8; ++nt) { C[nt][0] = C[nt][1] = C[nt][2] = C[nt][3] = 0.f; }
#pragma unroll
        for (int kk = 0; kk < 4; ++kk) {
            uint32_t a0 = ap[(g * 64 + kk * 16 + t * 2) >> 1];
            uint32_t a1 = ap[((g + 8) * 64 + kk * 16 + t * 2) >> 1];
            uint32_t a2 = ap[(g * 64 + kk * 16 + 8 + t * 2) >> 1];
            uint32_t a3 = ap[((g + 8) * 64 + kk * 16 + 8 + t * 2) >> 1];
#pragma unroll
            for (int nt = 0; nt < 8; ++nt)
                mma16816(C[nt], a0, a1, a2, a3, B0[kk][nt], B1[kk][nt]);
        }

        const int ra = rb + g, rbw = rb + g + 8;
        const int na = ra >> 6, ba = ra & 63;
        const int nb = rbw >> 6, bb = rbw & 63;
        float* oa = out + (size_t)ba * (NA * HD) + (size_t)na * 64 + t * 2;
        float* ob = out + (size_t)bb * (NA * HD) + (size_t)nb * 64 + t * 2;
#pragma unroll
        for (int nt = 0; nt < 8; ++nt) {
            *reinterpret_cast<float2*>(oa + nt * 8) =
                make_float2(tanhf(C[nt][0] + bv[nt].x), tanhf(C[nt][1] + bv[nt].y));
            *reinterpret_cast<float2*>(ob + nt * 8) =
                make_float2(tanhf(C[nt][2] + bv[nt].x), tanhf(C[nt][3] + bv[nt].y));
        }
    }
}

// ---------------------------------------------------------------------------

extern "C" void kernel_launch(void* const* d_in, const int* in_sizes, int n_in,
                              void* d_out, int out_size)
{
    const float* state = (const float*)d_in[0];
    const int*   ei    = (const int*)d_in[1];
    const float* W1  = (const float*)d_in[5];
    const float* b1  = (const float*)d_in[6];
    const float* W2  = (const float*)d_in[7];
    const float* b2  = (const float*)d_in[8];
    const float* W3  = (const float*)d_in[9];
    const float* b3  = (const float*)d_in[10];
    const float* g1  = (const float*)d_in[11];
    const float* be1 = (const float*)d_in[12];
    const float* g3  = (const float*)d_in[13];
    const float* be3 = (const float*)d_in[14];
    const float* Wf  = (const float*)d_in[15];
    const float* bf  = (const float*)d_in[16];
    float* out = (float*)d_out;

    const int E = in_sizes[1] / 2;

    float* pH1;
    __half *pH1h, *pH2h, *pH3h, *pPre, *pX, *pAX;
    cudaGetSymbolAddress((void**)&pH1,  g_h1);
    cudaGetSymbolAddress((void**)&pH1h, g_h1h);
    cudaGetSymbolAddress((void**)&pH2h, g_h2h);
    cudaGetSymbolAddress((void**)&pH3h, g_h3h);
    cudaGetSymbolAddress((void**)&pPre, g_pre);
    cudaGetSymbolAddress((void**)&pX,   g_X);
    cudaGetSymbolAddress((void**)&pAX,  g_AX);

    __half *pW2t, *pW3t;
    cudaGetSymbolAddress((void**)&pW2t, g_W2t);
    cudaGetSymbolAddress((void**)&pW3t, g_W3t);

    // graph preprocessing (CSR by dst, with self loops)
    init_deg_kernel<<<(NA + 255) / 256, 256>>>();
    count_kernel<<<(E + 255) / 256, 256>>>(ei, E);
    dinv_kernel<<<(NA + 255) / 256, 256>>>();
    scan_kernel<<<1, 1024>>>();
    fill_kernel<<<(E + NA + 255) / 256, 256>>>(ei, E);
    prep_w_kernel<<<(HD * HD + 255) / 256, 256>>>(W1, W2, W3, Wf);

    // conv1 = (A x) W1 : aggregate 16-feature input first
    transpose_kernel<<<(NA * CF + 255) / 256, 256>>>(state);
    agg16_kernel<<<NA, 128>>>(pX, pAX);
    hgemm16_ln_kernel<<<4736, 128>>>(pAX, b1, g1, be1, pH1, pH1h);

    // conv2: h2 = leaky(A (h1 W2) + b2) + h1
    hgemm64_kernel<<<4736, 128>>>(pH1h, pW2t, pPre);
    aggH_kernel<1><<<dim3(NA, 2), 128>>>(pPre, pH2h, b2, nullptr, nullptr);

    // conv3: h3 = leaky(LN(A (h2 W3) + b3)) + h1
    hgemm64_kernel<<<4736, 128>>>(pH2h, pW3t, pPre);
    aggH_kernel<2><<<dim3(NA, 2), 128>>>(pPre, pH3h, b3, g3, be3);

    // out = tanh(h3 Wf + bf), transposed back to [B, N*H]
    hgemm_final_kernel<<<4736, 128>>>(pH3h, bf, out);
}

// round 8
// speedup vs baseline: 2.5115x; 1.0413x over previous
#include <cuda_runtime.h>
#include <cuda_fp16.h>
#include <stdint.h>
#include <math.h>

// ---------------------------------------------------------------------------
// GNN_Encoder: 3x GCNConv (self-loops, sym-norm) + LN/leaky/residual + tanh
// B=64, N=10000, F=16, H=64, E=320000
// R8: R7 minus fp32 h1 side-traffic (residuals read fp16 h1), dinv folded
//     into scan. HMMA GEMMs, fp16 inter-stage buffers, fused epilogues.
// ---------------------------------------------------------------------------

namespace {
constexpr int NA = 10000;
constexpr int NF = 16;
constexpr int HD = 64;
constexpr int BT = 64;
constexpr int MR = NA * BT;        // 640000 rows ([node][batch] major)
constexpr int CH = BT * HD;        // 4096 hidden cols per node
constexpr int CF = BT * NF;        // 1024 input cols per node
constexpr int EMAX = 330000;
constexpr int NTILES = MR / 16;    // 40000 16-row mma tiles
}

// scratch (device globals; no allocation allowed)
__device__ __align__(256) __half g_h1h[MR * HD];      // h1 fp16
__device__ __align__(256) __half g_h2h[MR * HD];      // h2 fp16
__device__ __align__(256) __half g_h3h[MR * HD];      // h3 fp16
__device__ __align__(256) __half g_pre[MR * HD];      // pre-agg operand fp16
__device__ __align__(256) __half g_X[NA * CF];        // pre-scaled input fp16
__device__ __align__(256) __half g_AX[NA * CF];       // A·x fp16
__device__ __half g_W1t[HD * NF];   // [n][k] transposed fp16 weights
__device__ __half g_W2t[HD * HD];
__device__ __half g_W3t[HD * HD];
__device__ __half g_Wft[HD * HD];
__device__ int   g_deg[NA];
__device__ float g_dinv[NA];
__device__ int   g_rowptr[NA + 1];
__device__ int   g_fillptr[NA];
__device__ int   g_col[EMAX];

__device__ __forceinline__ float leaky(float x) {
    return x >= 0.f ? x : 0.01f * x;
}

__device__ __forceinline__ void mma16816(float c[4],
    uint32_t a0, uint32_t a1, uint32_t a2, uint32_t a3,
    uint32_t b0, uint32_t b1)
{
    asm volatile(
        "mma.sync.aligned.m16n8k16.row.col.f32.f16.f16.f32 "
        "{%0,%1,%2,%3},{%4,%5,%6,%7},{%8,%9},{%0,%1,%2,%3};"
        : "+f"(c[0]), "+f"(c[1]), "+f"(c[2]), "+f"(c[3])
        : "r"(a0), "r"(a1), "r"(a2), "r"(a3), "r"(b0), "r"(b1));
}

// ---------------- graph preprocessing ----------------

__global__ void init_deg_kernel() {
    int i = blockIdx.x * blockDim.x + threadIdx.x;
    if (i < NA) g_deg[i] = 1;
}

__global__ void count_kernel(const int* __restrict__ ei, int E) {
    int i = blockIdx.x * blockDim.x + threadIdx.x;
    if (i < E) atomicAdd(&g_deg[ei[E + i]], 1);
}

// scan of deg -> rowptr/fillptr, plus dinv = rsqrt(deg)
__global__ __launch_bounds__(1024) void scan_kernel() {
    __shared__ int warp_tot[32];
    const int tid  = threadIdx.x;
    const int lane = tid & 31;
    const int wid  = tid >> 5;
    const int base = tid * 10;

    int v[10];
    int run = 0;
#pragma unroll
    for (int k = 0; k < 10; ++k) {
        int i = base + k;
        int x = (i < NA) ? g_deg[i] : 0;
        if (i < NA) g_dinv[i] = rsqrtf((float)x);
        run += x;
        v[k] = run;
    }
    int s = run;
#pragma unroll
    for (int off = 1; off < 32; off <<= 1) {
        int y = __shfl_up_sync(0xffffffffu, s, off);
        if (lane >= off) s += y;
    }
    if (lane == 31) warp_tot[wid] = s;
    __syncthreads();
    if (wid == 0) {
        int w = warp_tot[lane];
#pragma unroll
        for (int off = 1; off < 32; off <<= 1) {
            int y = __shfl_up_sync(0xffffffffu, w, off);
            if (lane >= off) w += y;
        }
        warp_tot[lane] = w;
    }
    __syncthreads();
    const int warp_off = (wid == 0) ? 0 : warp_tot[wid - 1];
    const int excl = warp_off + (s - run);
    if (tid == 0) g_rowptr[0] = 0;
#pragma unroll
    for (int k = 0; k < 10; ++k) {
        int i = base + k;
        if (i < NA) {
            g_rowptr[i + 1] = excl + v[k];
            g_fillptr[i]    = excl + (k ? v[k - 1] : 0);
        }
    }
}

__global__ void fill_kernel(const int* __restrict__ ei, int E) {
    int i = blockIdx.x * blockDim.x + threadIdx.x;
    if (i < E) {
        int d = ei[E + i];
        int pos = atomicAdd(&g_fillptr[d], 1);
        g_col[pos] = ei[i];
    } else if (i < E + NA) {
        int n = i - E;
        int pos = atomicAdd(&g_fillptr[n], 1);
        g_col[pos] = n;
    }
}

// ---------------- weight prep: fp16 transposed [n][k]
__global__ void prep_w_kernel(const float* __restrict__ W1,
                              const float* __restrict__ W2,
                              const float* __restrict__ W3,
                              const float* __restrict__ Wf)
{
    int i = blockIdx.x * blockDim.x + threadIdx.x;
    if (i < HD * HD) {
        int n = i / HD, k = i % HD;
        g_W2t[i] = __float2half(W2[k * HD + n]);
        g_W3t[i] = __float2half(W3[k * HD + n]);
        g_Wft[i] = __float2half(Wf[k * HD + n]);
    }
    if (i < HD * NF) {
        int n = i / NF, k = i % NF;
        g_W1t[i] = __float2half(W1[k * HD + n]);
    }
}

// ---------------- transpose + pre-scale: state[b, n*16+f] -> X[n][b][f]*dinv[n]
__global__ void transpose_kernel(const float* __restrict__ state) {
    int i = blockIdx.x * blockDim.x + threadIdx.x;
    if (i < NA * CF) {
        int f = i & 15;
        int b = (i >> 4) & 63;
        int n = i >> 10;
        g_X[i] = __float2half(state[(size_t)b * (NA * NF) + n * NF + f] * g_dinv[n]);
    }
}

// ---------------- conv1 aggregation: AX[d] = dinv[d] * sum_s X[s] (fp16 out)
__global__ __launch_bounds__(128) void agg16_kernel(
    const __half* __restrict__ src, __half* __restrict__ dst)
{
    const int d = blockIdx.x;
    const int c = threadIdx.x * 8;
    float acc[8];
#pragma unroll
    for (int k = 0; k < 8; ++k) acc[k] = 0.f;

    const int beg = g_rowptr[d], end = g_rowptr[d + 1];
#pragma unroll 4
    for (int j = beg; j < end; ++j) {
        const int s = g_col[j];
        float4 u = *reinterpret_cast<const float4*>(src + (size_t)s * CF + c);
        const __half2* h = reinterpret_cast<const __half2*>(&u);
#pragma unroll
        for (int k = 0; k < 4; ++k) {
            float2 f = __half22float2(h[k]);
            acc[2 * k]     += f.x;
            acc[2 * k + 1] += f.y;
        }
    }
    const float sc = g_dinv[d];
    __half2 o[4];
#pragma unroll
    for (int k = 0; k < 4; ++k)
        o[k] = __floats2half2_rn(acc[2 * k] * sc, acc[2 * k + 1] * sc);
    *reinterpret_cast<float4*>(dst + (size_t)d * CF + c) =
        *reinterpret_cast<const float4*>(o);
}

// ---------------- hidden aggregation (4096 fp16 cols, 2 chunks of 2048)
// MODE 1: +b2, leaky, +h1 -> h2 fp16
// MODE 2: +b3, LN(g3,be3), leaky, +h1 -> h3 fp16
template <int MODE>
__global__ __launch_bounds__(128) void aggH_kernel(
    const __half* __restrict__ src, __half* __restrict__ dst,
    const float* __restrict__ bias,
    const float* __restrict__ gma, const float* __restrict__ bta)
{
    const int d  = blockIdx.x;
    const int c0 = blockIdx.y * 2048 + threadIdx.x * 16;
    const int f0 = c0 & 63;

    float acc[16];
#pragma unroll
    for (int k = 0; k < 16; ++k) acc[k] = 0.f;

    const int beg = g_rowptr[d], end = g_rowptr[d + 1];
#pragma unroll 2
    for (int j = beg; j < end; ++j) {
        const int s = g_col[j];
        const __half* row = src + (size_t)s * CH + c0;
        float4 u0 = *reinterpret_cast<const float4*>(row);
        float4 u1 = *reinterpret_cast<const float4*>(row + 8);
        const __half2* h0 = reinterpret_cast<const __half2*>(&u0);
        const __half2* h1 = reinterpret_cast<const __half2*>(&u1);
#pragma unroll
        for (int k = 0; k < 4; ++k) {
            float2 a = __half22float2(h0[k]);
            float2 b = __half22float2(h1[k]);
            acc[2 * k]         += a.x;
            acc[2 * k + 1]     += a.y;
            acc[8 + 2 * k]     += b.x;
            acc[8 + 2 * k + 1] += b.y;
        }
    }

    const float sc = g_dinv[d];
    float v[16];
#pragma unroll
    for (int k = 0; k < 16; ++k) v[k] = fmaf(acc[k], sc, bias[f0 + k]);

    // fp16 h1 residual (16 halves = 2x float4)
    const __half* h1p = g_h1h + (size_t)d * CH + c0;
    float4 r0 = *reinterpret_cast<const float4*>(h1p);
    float4 r1 = *reinterpret_cast<const float4*>(h1p + 8);
    float h1v[16];
    {
        const __half2* p0 = reinterpret_cast<const __half2*>(&r0);
        const __half2* p1 = reinterpret_cast<const __half2*>(&r1);
#pragma unroll
        for (int k = 0; k < 4; ++k) {
            float2 a = __half22float2(p0[k]);
            float2 b = __half22float2(p1[k]);
            h1v[2 * k]         = a.x;
            h1v[2 * k + 1]     = a.y;
            h1v[8 + 2 * k]     = b.x;
            h1v[8 + 2 * k + 1] = b.y;
        }
    }

    float out[16];
    if (MODE == 1) {
#pragma unroll
        for (int k = 0; k < 16; ++k) out[k] = leaky(v[k]) + h1v[k];
    } else {
        float s1 = 0.f, s2 = 0.f;
#pragma unroll
        for (int k = 0; k < 16; ++k) { s1 += v[k]; s2 += v[k] * v[k]; }
        s1 += __shfl_xor_sync(0xffffffffu, s1, 1);
        s2 += __shfl_xor_sync(0xffffffffu, s2, 1);
        s1 += __shfl_xor_sync(0xffffffffu, s1, 2);
        s2 += __shfl_xor_sync(0xffffffffu, s2, 2);
        const float mean = s1 * (1.f / 64.f);
        const float var  = fmaf(s2, 1.f / 64.f, -mean * mean);
        const float rs   = rsqrtf(var + 1e-5f);
#pragma unroll
        for (int k = 0; k < 16; ++k)
            out[k] = leaky(fmaf((v[k] - mean) * rs, gma[f0 + k], bta[f0 + k])) + h1v[k];
    }

    __half2 o[8];
#pragma unroll
    for (int k = 0; k < 8; ++k)
        o[k] = __floats2half2_rn(out[2 * k], out[2 * k + 1]);
    float4* op = reinterpret_cast<float4*>(dst + (size_t)d * CH + c0);
    op[0] = reinterpret_cast<const float4*>(o)[0];
    op[1] = reinterpret_cast<const float4*>(o)[1];
}

// ---------------- HMMA GEMM K=16 + bias + LN + leaky -> h1 fp16
__global__ __launch_bounds__(128) void hgemm16_ln_kernel(
    const __half* __restrict__ in, const float* __restrict__ bias,
    const float* __restrict__ gma, const float* __restrict__ bta,
    __half* __restrict__ out16)
{
    const int lane = threadIdx.x & 31;
    const int g = lane >> 2, t = lane & 3;

    // B frags (K=16: one k-step), col n = nt*8+g, k = t*2 (+8)
    uint32_t B0[8], B1[8];
    const uint32_t* wp = reinterpret_cast<const uint32_t*>(g_W1t);
#pragma unroll
    for (int nt = 0; nt < 8; ++nt) {
        B0[nt] = wp[((nt * 8 + g) * 16 + t * 2) >> 1];
        B1[nt] = wp[((nt * 8 + g) * 16 + 8 + t * 2) >> 1];
    }
    // per-lane epilogue params, cols nt*8 + t*2 + {0,1}
    float2 bv[8], gv[8], ev[8];
#pragma unroll
    for (int nt = 0; nt < 8; ++nt) {
        bv[nt] = *reinterpret_cast<const float2*>(bias + nt * 8 + t * 2);
        gv[nt] = *reinterpret_cast<const float2*>(gma  + nt * 8 + t * 2);
        ev[nt] = *reinterpret_cast<const float2*>(bta  + nt * 8 + t * 2);
    }

    const int warp = (blockIdx.x * blockDim.x + threadIdx.x) >> 5;
    const int nw   = (gridDim.x * blockDim.x) >> 5;
    for (int tile = warp; tile < NTILES; tile += nw) {
        const int rb = tile * 16;
        const uint32_t* ap = reinterpret_cast<const uint32_t*>(in + (size_t)rb * 16);
        uint32_t a0 = ap[(g * 16 + t * 2) >> 1];
        uint32_t a1 = ap[((g + 8) * 16 + t * 2) >> 1];
        uint32_t a2 = ap[(g * 16 + 8 + t * 2) >> 1];
        uint32_t a3 = ap[((g + 8) * 16 + 8 + t * 2) >> 1];

        float C[8][4];
#pragma unroll
        for (int nt = 0; nt < 8; ++nt) { C[nt][0] = C[nt][1] = C[nt][2] = C[nt][3] = 0.f; }
#pragma unroll
        for (int nt = 0; nt < 8; ++nt)
            mma16816(C[nt], a0, a1, a2, a3, B0[nt], B1[nt]);

        // + bias
        float va[16], vb[16];   // row g (a), row g+8 (b); 2 vals per nt
#pragma unroll
        for (int nt = 0; nt < 8; ++nt) {
            va[2 * nt]     = C[nt][0] + bv[nt].x;
            va[2 * nt + 1] = C[nt][1] + bv[nt].y;
            vb[2 * nt]     = C[nt][2] + bv[nt].x;
            vb[2 * nt + 1] = C[nt][3] + bv[nt].y;
        }
        // LN per row across the 4 lanes of this row group
        float s1a = 0.f, s2a = 0.f, s1b = 0.f, s2b = 0.f;
#pragma unroll
        for (int k = 0; k < 16; ++k) {
            s1a += va[k]; s2a += va[k] * va[k];
            s1b += vb[k]; s2b += vb[k] * vb[k];
        }
#pragma unroll
        for (int off = 1; off <= 2; off <<= 1) {
            s1a += __shfl_xor_sync(0xffffffffu, s1a, off);
            s2a += __shfl_xor_sync(0xffffffffu, s2a, off);
            s1b += __shfl_xor_sync(0xffffffffu, s1b, off);
            s2b += __shfl_xor_sync(0xffffffffu, s2b, off);
        }
        const float ma = s1a * (1.f / 64.f);
        const float ra = rsqrtf(fmaf(s2a, 1.f / 64.f, -ma * ma) + 1e-5f);
        const float mb = s1b * (1.f / 64.f);
        const float rbv = rsqrtf(fmaf(s2b, 1.f / 64.f, -mb * mb) + 1e-5f);

        __half* oa16 = out16 + (size_t)(rb + g) * 64 + t * 2;
        __half* ob16 = out16 + (size_t)(rb + g + 8) * 64 + t * 2;
#pragma unroll
        for (int nt = 0; nt < 8; ++nt) {
            float x0 = leaky(fmaf((va[2 * nt]     - ma) * ra, gv[nt].x, ev[nt].x));
            float x1 = leaky(fmaf((va[2 * nt + 1] - ma) * ra, gv[nt].y, ev[nt].y));
            float y0 = leaky(fmaf((vb[2 * nt]     - mb) * rbv, gv[nt].x, ev[nt].x));
            float y1 = leaky(fmaf((vb[2 * nt + 1] - mb) * rbv, gv[nt].y, ev[nt].y));
            *reinterpret_cast<__half2*>(oa16 + nt * 8) = __floats2half2_rn(x0, x1);
            *reinterpret_cast<__half2*>(ob16 + nt * 8) = __floats2half2_rn(y0, y1);
        }
    }
}

// ---------------- HMMA GEMM K=64, epilogue * dinv[node] -> fp16
__global__ __launch_bounds__(128) void hgemm64_kernel(
    const __half* __restrict__ in, const __half* __restrict__ Wt,
    __half* __restrict__ out)
{
    const int lane = threadIdx.x & 31;
    const int g = lane >> 2, t = lane & 3;

    uint32_t B0[4][8], B1[4][8];
    const uint32_t* wp = reinterpret_cast<const uint32_t*>(Wt);
#pragma unroll
    for (int kk = 0; kk < 4; ++kk)
#pragma unroll
        for (int nt = 0; nt < 8; ++nt) {
            B0[kk][nt] = wp[((nt * 8 + g) * 64 + kk * 16 + t * 2) >> 1];
            B1[kk][nt] = wp[((nt * 8 + g) * 64 + kk * 16 + 8 + t * 2) >> 1];
        }

    const int warp = (blockIdx.x * blockDim.x + threadIdx.x) >> 5;
    const int nw   = (gridDim.x * blockDim.x) >> 5;
    for (int tile = warp; tile < NTILES; tile += nw) {
        const int rb = tile * 16;
        const uint32_t* ap = reinterpret_cast<const uint32_t*>(in + (size_t)rb * 64);

        float C[8][4];
#pragma unroll
        for (int nt = 0; nt < 8; ++nt) { C[nt][0] = C[nt][1] = C[nt][2] = C[nt][3] = 0.f; }
#pragma unroll
        for (int kk = 0; kk < 4; ++kk) {
            uint32_t a0 = ap[(g * 64 + kk * 16 + t * 2) >> 1];
            uint32_t a1 = ap[((g + 8) * 64 + kk * 16 + t * 2) >> 1];
            uint32_t a2 = ap[(g * 64 + kk * 16 + 8 + t * 2) >> 1];
            uint32_t a3 = ap[((g + 8) * 64 + kk * 16 + 8 + t * 2) >> 1];
#pragma unroll
            for (int nt = 0; nt < 8; ++nt)
                mma16816(C[nt], a0, a1, a2, a3, B0[kk][nt], B1[kk][nt]);
        }

        const float s = g_dinv[rb >> 6];
        __half* oa = out + (size_t)(rb + g) * 64 + t * 2;
        __half* ob = out + (size_t)(rb + g + 8) * 64 + t * 2;
#pragma unroll
        for (int nt = 0; nt < 8; ++nt) {
            *reinterpret_cast<__half2*>(oa + nt * 8) =
                __floats2half2_rn(C[nt][0] * s, C[nt][1] * s);
            *reinterpret_cast<__half2*>(ob + nt * 8) =
                __floats2half2_rn(C[nt][2] * s, C[nt][3] * s);
        }
    }
}

// ---------------- HMMA final GEMM K=64 + bias + tanh, transposed store
__global__ __launch_bounds__(128) void hgemm_final_kernel(
    const __half* __restrict__ in, const float* __restrict__ bias,
    float* __restrict__ out)
{
    const int lane = threadIdx.x & 31;
    const int g = lane >> 2, t = lane & 3;

    uint32_t B0[4][8], B1[4][8];
    const uint32_t* wp = reinterpret_cast<const uint32_t*>(g_Wft);
#pragma unroll
    for (int kk = 0; kk < 4; ++kk)
#pragma unroll
        for (int nt = 0; nt < 8; ++nt) {
            B0[kk][nt] = wp[((nt * 8 + g) * 64 + kk * 16 + t * 2) >> 1];
            B1[kk][nt] = wp[((nt * 8 + g) * 64 + kk * 16 + 8 + t * 2) >> 1];
        }
    float2 bv[8];
#pragma unroll
    for (int nt = 0; nt < 8; ++nt)
        bv[nt] = *reinterpret_cast<const float2*>(bias + nt * 8 + t * 2);

    const int warp = (blockIdx.x * blockDim.x + threadIdx.x) >> 5;
    const int nw   = (gridDim.x * blockDim.x) >> 5;
    for (int tile = warp; tile < NTILES; tile += nw) {
        const int rb = tile * 16;
        const uint32_t* ap = reinterpret_cast<const uint32_t*>(in + (size_t)rb * 64);

        float C[8][4];
#pragma unroll
        for (int nt = 0; nt < 8; ++nt) { C[nt][0] = C[nt][1] = C[nt][2] = C[nt][3] = 0.f; }
#pragma unroll
        for (int kk = 0; kk < 4; ++kk) {
            uint32_t a0 = ap[(g * 64 + kk * 16 + t * 2) >> 1];
            uint32_t a1 = ap[((g + 8) * 64 + kk * 16 + t * 2) >> 1];
            uint32_t a2 = ap[(g * 64 + kk * 16 + 8 + t * 2) >> 1];
            uint32_t a3 = ap[((g + 8) * 64 + kk * 16 + 8 + t * 2) >> 1];
#pragma unroll
            for (int nt = 0; nt < 8; ++nt)
                mma16816(C[nt], a0, a1, a2, a3, B0[kk][nt], B1[kk][nt]);
        }

        const int ra = rb + g, rbw = rb + g + 8;
        const int na = ra >> 6, ba = ra & 63;
        const int nb = rbw >> 6, bb = rbw & 63;
        float* oa = out + (size_t)ba * (NA * HD) + (size_t)na * 64 + t * 2;
        float* ob = out + (size_t)bb * (NA * HD) + (size_t)nb * 64 + t * 2;
#pragma unroll
        for (int nt = 0; nt < 8; ++nt) {
            *reinterpret_cast<float2*>(oa + nt * 8) =
                make_float2(tanhf(C[nt][0] + bv[nt].x), tanhf(C[nt][1] + bv[nt].y));
            *reinterpret_cast<float2*>(ob + nt * 8) =
                make_float2(tanhf(C[nt][2] + bv[nt].x), tanhf(C[nt][3] + bv[nt].y));
        }
    }
}

// ---------------------------------------------------------------------------

extern "C" void kernel_launch(void* const* d_in, const int* in_sizes, int n_in,
                              void* d_out, int out_size)
{
    const float* state = (const float*)d_in[0];
    const int*   ei    = (const int*)d_in[1];
    const float* W1  = (const float*)d_in[5];
    const float* b1  = (const float*)d_in[6];
    const float* W2  = (const float*)d_in[7];
    const float* b2  = (const float*)d_in[8];
    const float* W3  = (const float*)d_in[9];
    const float* b3  = (const float*)d_in[10];
    const float* g1  = (const float*)d_in[11];
    const float* be1 = (const float*)d_in[12];
    const float* g3  = (const float*)d_in[13];
    const float* be3 = (const float*)d_in[14];
    const float* Wf  = (const float*)d_in[15];
    const float* bf  = (const float*)d_in[16];
    float* out = (float*)d_out;

    const int E = in_sizes[1] / 2;

    __half *pH1h, *pH2h, *pH3h, *pPre, *pX, *pAX;
    cudaGetSymbolAddress((void**)&pH1h, g_h1h);
    cudaGetSymbolAddress((void**)&pH2h, g_h2h);
    cudaGetSymbolAddress((void**)&pH3h, g_h3h);
    cudaGetSymbolAddress((void**)&pPre, g_pre);
    cudaGetSymbolAddress((void**)&pX,   g_X);
    cudaGetSymbolAddress((void**)&pAX,  g_AX);

    __half *pW2t, *pW3t;
    cudaGetSymbolAddress((void**)&pW2t, g_W2t);
    cudaGetSymbolAddress((void**)&pW3t, g_W3t);

    // graph preprocessing (CSR by dst, with self loops)
    init_deg_kernel<<<(NA + 255) / 256, 256>>>();
    count_kernel<<<(E + 255) / 256, 256>>>(ei, E);
    scan_kernel<<<1, 1024>>>();                       // rowptr/fillptr + dinv
    fill_kernel<<<(E + NA + 255) / 256, 256>>>(ei, E);
    prep_w_kernel<<<(HD * HD + 255) / 256, 256>>>(W1, W2, W3, Wf);

    // conv1 = (A x) W1 : aggregate 16-feature input first
    transpose_kernel<<<(NA * CF + 255) / 256, 256>>>(state);
    agg16_kernel<<<NA, 128>>>(pX, pAX);
    hgemm16_ln_kernel<<<4736, 128>>>(pAX, b1, g1, be1, pH1h);

    // conv2: h2 = leaky(A (h1 W2) + b2) + h1
    hgemm64_kernel<<<4736, 128>>>(pH1h, pW2t, pPre);
    aggH_kernel<1><<<dim3(NA, 2), 128>>>(pPre, pH2h, b2, nullptr, nullptr);

    // conv3: h3 = leaky(LN(A (h2 W3) + b3)) + h1
    hgemm64_kernel<<<4736, 128>>>(pH2h, pW3t, pPre);
    aggH_kernel<2><<<dim3(NA, 2), 128>>>(pPre, pH3h, b3, g3, be3);

    // out = tanh(h3 Wf + bf), transposed back to [B, N*H]
    hgemm_final_kernel<<<4736, 128>>>(pH3h, bf, out);
}

// round 9
// speedup vs baseline: 2.5377x; 1.0104x over previous
#include <cuda_runtime.h>
#include <cuda_fp16.h>
#include <stdint.h>
#include <math.h>

// ---------------------------------------------------------------------------
// GNN_Encoder: 3x GCNConv (self-loops, sym-norm) + LN/leaky/residual + tanh
// B=64, N=10000, F=16, H=64, E=320000
// R9: R8 + (a) W2 GEMM fused into hgemm16_ln via C-frag==A-frag reuse,
//     (b) self-loops emitted by scan (memset+count, fill handles edges only),
//     (c) prep_w merged into transpose, (d) aggH unroll 4.
// ---------------------------------------------------------------------------

namespace {
constexpr int NA = 10000;
constexpr int NF = 16;
constexpr int HD = 64;
constexpr int BT = 64;
constexpr int MR = NA * BT;        // 640000 rows ([node][batch] major)
constexpr int CH = BT * HD;        // 4096 hidden cols per node
constexpr int CF = BT * NF;        // 1024 input cols per node
constexpr int EMAX = 330000;
constexpr int NTILES = MR / 16;    // 40000 16-row mma tiles
}

// scratch (device globals; no allocation allowed)
__device__ __align__(256) __half g_h1h[MR * HD];      // h1 fp16
__device__ __align__(256) __half g_h2h[MR * HD];      // h2 fp16
__device__ __align__(256) __half g_h3h[MR * HD];      // h3 fp16
__device__ __align__(256) __half g_pre[MR * HD];      // pre-agg operand fp16
__device__ __align__(256) __half g_X[NA * CF];        // pre-scaled input fp16
__device__ __align__(256) __half g_AX[NA * CF];       // A·x fp16
__device__ __half g_W1t[HD * NF];   // [n][k] transposed fp16 weights
__device__ __half g_W2t[HD * HD];
__device__ __half g_W3t[HD * HD];
__device__ __half g_Wft[HD * HD];
__device__ int   g_deg[NA];
__device__ float g_dinv[NA];
__device__ int   g_rowptr[NA + 1];
__device__ int   g_fillptr[NA];
__device__ int   g_col[EMAX];

__device__ __forceinline__ float leaky(float x) {
    return x >= 0.f ? x : 0.01f * x;
}

__device__ __forceinline__ void mma16816(float c[4],
    uint32_t a0, uint32_t a1, uint32_t a2, uint32_t a3,
    uint32_t b0, uint32_t b1)
{
    asm volatile(
        "mma.sync.aligned.m16n8k16.row.col.f32.f16.f16.f32 "
        "{%0,%1,%2,%3},{%4,%5,%6,%7},{%8,%9},{%0,%1,%2,%3};"
        : "+f"(c[0]), "+f"(c[1]), "+f"(c[2]), "+f"(c[3])
        : "r"(a0), "r"(a1), "r"(a2), "r"(a3), "r"(b0), "r"(b1));
}

// ---------------- graph preprocessing ----------------

// g_deg was memset to 0; count edges by dst
__global__ void count_kernel(const int* __restrict__ ei, int E) {
    int i = blockIdx.x * blockDim.x + threadIdx.x;
    if (i < E) atomicAdd(&g_deg[ei[E + i]], 1);
}

// scan of (deg+1) -> rowptr, fillptr=rowptr+1, self-loop col entry, dinv
__global__ __launch_bounds__(1024) void scan_kernel() {
    __shared__ int warp_tot[32];
    const int tid  = threadIdx.x;
    const int lane = tid & 31;
    const int wid  = tid >> 5;
    const int base = tid * 10;

    int v[10];
    int run = 0;
#pragma unroll
    for (int k = 0; k < 10; ++k) {
        int i = base + k;
        int x = (i < NA) ? (g_deg[i] + 1) : 0;   // +1 self loop
        if (i < NA) g_dinv[i] = rsqrtf((float)x);
        run += x;
        v[k] = run;
    }
    int s = run;
#pragma unroll
    for (int off = 1; off < 32; off <<= 1) {
        int y = __shfl_up_sync(0xffffffffu, s, off);
        if (lane >= off) s += y;
    }
    if (lane == 31) warp_tot[wid] = s;
    __syncthreads();
    if (wid == 0) {
        int w = warp_tot[lane];
#pragma unroll
        for (int off = 1; off < 32; off <<= 1) {
            int y = __shfl_up_sync(0xffffffffu, w, off);
            if (lane >= off) w += y;
        }
        warp_tot[lane] = w;
    }
    __syncthreads();
    const int warp_off = (wid == 0) ? 0 : warp_tot[wid - 1];
    const int excl = warp_off + (s - run);
    if (tid == 0) g_rowptr[0] = 0;
#pragma unroll
    for (int k = 0; k < 10; ++k) {
        int i = base + k;
        if (i < NA) {
            int rbeg = excl + (k ? v[k - 1] : 0);
            g_rowptr[i + 1] = excl + v[k];
            g_col[rbeg]     = i;           // self loop first
            g_fillptr[i]    = rbeg + 1;    // edges after it
        }
    }
}

__global__ void fill_kernel(const int* __restrict__ ei, int E) {
    int i = blockIdx.x * blockDim.x + threadIdx.x;
    if (i < E) {
        int d = ei[E + i];
        int pos = atomicAdd(&g_fillptr[d], 1);
        g_col[pos] = ei[i];
    }
}

// ---------------- transpose + pre-scale + weight prep (merged)
// state[b, n*16+f] -> X[n][b][f]*dinv[n] ; first 4096 threads also do weights
__global__ void transpose_prep_kernel(const float* __restrict__ state,
                                      const float* __restrict__ W1,
                                      const float* __restrict__ W2,
                                      const float* __restrict__ W3,
                                      const float* __restrict__ Wf)
{
    int i = blockIdx.x * blockDim.x + threadIdx.x;
    if (i < HD * HD) {
        int n = i / HD, k = i % HD;
        g_W2t[i] = __float2half(W2[k * HD + n]);
        g_W3t[i] = __float2half(W3[k * HD + n]);
        g_Wft[i] = __float2half(Wf[k * HD + n]);
        if (i < HD * NF) {
            int n1 = i / NF, k1 = i % NF;
            g_W1t[i] = __float2half(W1[k1 * HD + n1]);
        }
    }
    if (i < NA * CF) {
        int f = i & 15;
        int b = (i >> 4) & 63;
        int n = i >> 10;
        g_X[i] = __float2half(state[(size_t)b * (NA * NF) + n * NF + f] * g_dinv[n]);
    }
}

// ---------------- conv1 aggregation: AX[d] = dinv[d] * sum_s X[s] (fp16 out)
__global__ __launch_bounds__(128) void agg16_kernel(
    const __half* __restrict__ src, __half* __restrict__ dst)
{
    const int d = blockIdx.x;
    const int c = threadIdx.x * 8;
    float acc[8];
#pragma unroll
    for (int k = 0; k < 8; ++k) acc[k] = 0.f;

    const int beg = g_rowptr[d], end = g_rowptr[d + 1];
#pragma unroll 4
    for (int j = beg; j < end; ++j) {
        const int s = g_col[j];
        float4 u = *reinterpret_cast<const float4*>(src + (size_t)s * CF + c);
        const __half2* h = reinterpret_cast<const __half2*>(&u);
#pragma unroll
        for (int k = 0; k < 4; ++k) {
            float2 f = __half22float2(h[k]);
            acc[2 * k]     += f.x;
            acc[2 * k + 1] += f.y;
        }
    }
    const float sc = g_dinv[d];
    __half2 o[4];
#pragma unroll
    for (int k = 0; k < 4; ++k)
        o[k] = __floats2half2_rn(acc[2 * k] * sc, acc[2 * k + 1] * sc);
    *reinterpret_cast<float4*>(dst + (size_t)d * CF + c) =
        *reinterpret_cast<const float4*>(o);
}

// ---------------- hidden aggregation (4096 fp16 cols, 2 chunks of 2048)
// MODE 1: +b2, leaky, +h1 -> h2 fp16
// MODE 2: +b3, LN(g3,be3), leaky, +h1 -> h3 fp16
template <int MODE>
__global__ __launch_bounds__(128) void aggH_kernel(
    const __half* __restrict__ src, __half* __restrict__ dst,
    const float* __restrict__ bias,
    const float* __restrict__ gma, const float* __restrict__ bta)
{
    const int d  = blockIdx.x;
    const int c0 = blockIdx.y * 2048 + threadIdx.x * 16;
    const int f0 = c0 & 63;

    float acc[16];
#pragma unroll
    for (int k = 0; k < 16; ++k) acc[k] = 0.f;

    const int beg = g_rowptr[d], end = g_rowptr[d + 1];
#pragma unroll 4
    for (int j = beg; j < end; ++j) {
        const int s = g_col[j];
        const __half* row = src + (size_t)s * CH + c0;
        float4 u0 = *reinterpret_cast<const float4*>(row);
        float4 u1 = *reinterpret_cast<const float4*>(row + 8);
        const __half2* h0 = reinterpret_cast<const __half2*>(&u0);
        const __half2* h1 = reinterpret_cast<const __half2*>(&u1);
#pragma unroll
        for (int k = 0; k < 4; ++k) {
            float2 a = __half22float2(h0[k]);
            float2 b = __half22float2(h1[k]);
            acc[2 * k]         += a.x;
            acc[2 * k + 1]     += a.y;
            acc[8 + 2 * k]     += b.x;
            acc[8 + 2 * k + 1] += b.y;
        }
    }

    const float sc = g_dinv[d];
    float v[16];
#pragma unroll
    for (int k = 0; k < 16; ++k) v[k] = fmaf(acc[k], sc, bias[f0 + k]);

    // fp16 h1 residual (16 halves = 2x float4)
    const __half* h1p = g_h1h + (size_t)d * CH + c0;
    float4 r0 = *reinterpret_cast<const float4*>(h1p);
    float4 r1 = *reinterpret_cast<const float4*>(h1p + 8);
    float h1v[16];
    {
        const __half2* p0 = reinterpret_cast<const __half2*>(&r0);
        const __half2* p1 = reinterpret_cast<const __half2*>(&r1);
#pragma unroll
        for (int k = 0; k < 4; ++k) {
            float2 a = __half22float2(p0[k]);
            float2 b = __half22float2(p1[k]);
            h1v[2 * k]         = a.x;
            h1v[2 * k + 1]     = a.y;
            h1v[8 + 2 * k]     = b.x;
            h1v[8 + 2 * k + 1] = b.y;
        }
    }

    float out[16];
    if (MODE == 1) {
#pragma unroll
        for (int k = 0; k < 16; ++k) out[k] = leaky(v[k]) + h1v[k];
    } else {
        float s1 = 0.f, s2 = 0.f;
#pragma unroll
        for (int k = 0; k < 16; ++k) { s1 += v[k]; s2 += v[k] * v[k]; }
        s1 += __shfl_xor_sync(0xffffffffu, s1, 1);
        s2 += __shfl_xor_sync(0xffffffffu, s2, 1);
        s1 += __shfl_xor_sync(0xffffffffu, s1, 2);
        s2 += __shfl_xor_sync(0xffffffffu, s2, 2);
        const float mean = s1 * (1.f / 64.f);
        const float var  = fmaf(s2, 1.f / 64.f, -mean * mean);
        const float rs   = rsqrtf(var + 1e-5f);
#pragma unroll
        for (int k = 0; k < 16; ++k)
            out[k] = leaky(fmaf((v[k] - mean) * rs, gma[f0 + k], bta[f0 + k])) + h1v[k];
    }

    __half2 o[8];
#pragma unroll
    for (int k = 0; k < 8; ++k)
        o[k] = __floats2half2_rn(out[2 * k], out[2 * k + 1]);
    float4* op = reinterpret_cast<float4*>(dst + (size_t)d * CH + c0);
    op[0] = reinterpret_cast<const float4*>(o)[0];
    op[1] = reinterpret_cast<const float4*>(o)[1];
}

// ---------------- HMMA GEMM K=16 + bias + LN + leaky -> h1 fp16,
// then fused W2 GEMM on the in-register h1 (C-frag == A-frag layout),
// epilogue * dinv[node] -> g_pre fp16
__global__ __launch_bounds__(128) void hgemm16_ln_w2_kernel(
    const __half* __restrict__ in, const float* __restrict__ bias,
    const float* __restrict__ gma, const float* __restrict__ bta,
    __half* __restrict__ out_h1, __half* __restrict__ out_pre)
{
    const int lane = threadIdx.x & 31;
    const int g = lane >> 2, t = lane & 3;

    // W1 B-frags (K=16: one k-step), col n = nt*8+g, k = t*2 (+8)
    uint32_t B0[8], B1[8];
    {
        const uint32_t* wp = reinterpret_cast<const uint32_t*>(g_W1t);
#pragma unroll
        for (int nt = 0; nt < 8; ++nt) {
            B0[nt] = wp[((nt * 8 + g) * 16 + t * 2) >> 1];
            B1[nt] = wp[((nt * 8 + g) * 16 + 8 + t * 2) >> 1];
        }
    }
    // W2 B-frags (K=64: 4 k-steps)
    uint32_t W20[4][8], W21[4][8];
    {
        const uint32_t* wp = reinterpret_cast<const uint32_t*>(g_W2t);
#pragma unroll
        for (int kk = 0; kk < 4; ++kk)
#pragma unroll
            for (int nt = 0; nt < 8; ++nt) {
                W20[kk][nt] = wp[((nt * 8 + g) * 64 + kk * 16 + t * 2) >> 1];
                W21[kk][nt] = wp[((nt * 8 + g) * 64 + kk * 16 + 8 + t * 2) >> 1];
            }
    }

    const int warp = (blockIdx.x * blockDim.x + threadIdx.x) >> 5;
    const int nw   = (gridDim.x * blockDim.x) >> 5;
    for (int tile = warp; tile < NTILES; tile += nw) {
        const int rb = tile * 16;
        const uint32_t* ap = reinterpret_cast<const uint32_t*>(in + (size_t)rb * 16);
        uint32_t a0 = ap[(g * 16 + t * 2) >> 1];
        uint32_t a1 = ap[((g + 8) * 16 + t * 2) >> 1];
        uint32_t a2 = ap[(g * 16 + 8 + t * 2) >> 1];
        uint32_t a3 = ap[((g + 8) * 16 + 8 + t * 2) >> 1];

        float C[8][4];
#pragma unroll
        for (int nt = 0; nt < 8; ++nt) { C[nt][0] = C[nt][1] = C[nt][2] = C[nt][3] = 0.f; }
#pragma unroll
        for (int nt = 0; nt < 8; ++nt)
            mma16816(C[nt], a0, a1, a2, a3, B0[nt], B1[nt]);

        // bias + LN + leaky epilogue (params loaded per tile to cap registers)
        float va[16], vb[16];
#pragma unroll
        for (int nt = 0; nt < 8; ++nt) {
            float2 bv = *reinterpret_cast<const float2*>(bias + nt * 8 + t * 2);
            va[2 * nt]     = C[nt][0] + bv.x;
            va[2 * nt + 1] = C[nt][1] + bv.y;
            vb[2 * nt]     = C[nt][2] + bv.x;
            vb[2 * nt + 1] = C[nt][3] + bv.y;
        }
        float s1a = 0.f, s2a = 0.f, s1b = 0.f, s2b = 0.f;
#pragma unroll
        for (int k = 0; k < 16; ++k) {
            s1a += va[k]; s2a += va[k] * va[k];
            s1b += vb[k]; s2b += vb[k] * vb[k];
        }
#pragma unroll
        for (int off = 1; off <= 2; off <<= 1) {
            s1a += __shfl_xor_sync(0xffffffffu, s1a, off);
            s2a += __shfl_xor_sync(0xffffffffu, s2a, off);
            s1b += __shfl_xor_sync(0xffffffffu, s1b, off);
            s2b += __shfl_xor_sync(0xffffffffu, s2b, off);
        }
        const float ma = s1a * (1.f / 64.f);
        const float ra = rsqrtf(fmaf(s2a, 1.f / 64.f, -ma * ma) + 1e-5f);
        const float mb = s1b * (1.f / 64.f);
        const float rbv = rsqrtf(fmaf(s2b, 1.f / 64.f, -mb * mb) + 1e-5f);

        // h1 as fp16 packs: ha[nt] = cols (8nt+2t, +1) of row g; hb: row g+8
        uint32_t ha[8], hb[8];
#pragma unroll
        for (int nt = 0; nt < 8; ++nt) {
            float2 gv = *reinterpret_cast<const float2*>(gma + nt * 8 + t * 2);
            float2 ev = *reinterpret_cast<const float2*>(bta + nt * 8 + t * 2);
            float x0 = leaky(fmaf((va[2 * nt]     - ma) * ra, gv.x, ev.x));
            float x1 = leaky(fmaf((va[2 * nt + 1] - ma) * ra, gv.y, ev.y));
            float y0 = leaky(fmaf((vb[2 * nt]     - mb) * rbv, gv.x, ev.x));
            float y1 = leaky(fmaf((vb[2 * nt + 1] - mb) * rbv, gv.y, ev.y));
            __half2 hx = __floats2half2_rn(x0, x1);
            __half2 hy = __floats2half2_rn(y0, y1);
            ha[nt] = *reinterpret_cast<const uint32_t*>(&hx);
            hb[nt] = *reinterpret_cast<const uint32_t*>(&hy);
        }
        // store h1
        __half* oa16 = out_h1 + (size_t)(rb + g) * 64 + t * 2;
        __half* ob16 = out_h1 + (size_t)(rb + g + 8) * 64 + t * 2;
#pragma unroll
        for (int nt = 0; nt < 8; ++nt) {
            *reinterpret_cast<uint32_t*>(oa16 + nt * 8) = ha[nt];
            *reinterpret_cast<uint32_t*>(ob16 + nt * 8) = hb[nt];
        }

        // fused W2 GEMM: A-frag for k-block kk is (ha[2kk], hb[2kk], ha[2kk+1], hb[2kk+1])
        float C2[8][4];
#pragma unroll
        for (int nt = 0; nt < 8; ++nt) { C2[nt][0] = C2[nt][1] = C2[nt][2] = C2[nt][3] = 0.f; }
#pragma unroll
        for (int kk = 0; kk < 4; ++kk) {
#pragma unroll
            for (int nt = 0; nt < 8; ++nt)
                mma16816(C2[nt], ha[2 * kk], hb[2 * kk], ha[2 * kk + 1], hb[2 * kk + 1],
                         W20[kk][nt], W21[kk][nt]);
        }

        const float s = g_dinv[rb >> 6];
        __half* pa = out_pre + (size_t)(rb + g) * 64 + t * 2;
        __half* pb = out_pre + (size_t)(rb + g + 8) * 64 + t * 2;
#pragma unroll
        for (int nt = 0; nt < 8; ++nt) {
            *reinterpret_cast<__half2*>(pa + nt * 8) =
                __floats2half2_rn(C2[nt][0] * s, C2[nt][1] * s);
            *reinterpret_cast<__half2*>(pb + nt * 8) =
                __floats2half2_rn(C2[nt][2] * s, C2[nt][3] * s);
        }
    }
}

// ---------------- HMMA GEMM K=64, epilogue * dinv[node] -> fp16
__global__ __launch_bounds__(128) void hgemm64_kernel(
    const __half* __restrict__ in, const __half* __restrict__ Wt,
    __half* __restrict__ out)
{
    const int lane = threadIdx.x & 31;
    const int g = lane >> 2, t = lane & 3;

    uint32_t B0[4][8], B1[4][8];
    const uint32_t* wp = reinterpret_cast<const uint32_t*>(Wt);
#pragma unroll
    for (int kk = 0; kk < 4; ++kk)
#pragma unroll
        for (int nt = 0; nt < 8; ++nt) {
            B0[kk][nt] = wp[((nt * 8 + g) * 64 + kk * 16 + t * 2) >> 1];
            B1[kk][nt] = wp[((nt * 8 + g) * 64 + kk * 16 + 8 + t * 2) >> 1];
        }

    const int warp = (blockIdx.x * blockDim.x + threadIdx.x) >> 5;
    const int nw   = (gridDim.x * blockDim.x) >> 5;
    for (int tile = warp; tile < NTILES; tile += nw) {
        const int rb = tile * 16;
        const uint32_t* ap = reinterpret_cast<const uint32_t*>(in + (size_t)rb * 64);

        float C[8][4];
#pragma unroll
        for (int nt = 0; nt < 8; ++nt) { C[nt][0] = C[nt][1] = C[nt][2] = C[nt][3] = 0.f; }
#pragma unroll
        for (int kk = 0; kk < 4; ++kk) {
            uint32_t a0 = ap[(g * 64 + kk * 16 + t * 2) >> 1];
            uint32_t a1 = ap[((g + 8) * 64 + kk * 16 + t * 2) >> 1];
            uint32_t a2 = ap[(g * 64 + kk * 16 + 8 + t * 2) >> 1];
            uint32_t a3 = ap[((g + 8) * 64 + kk * 16 + 8 + t * 2) >> 1];
#pragma unroll
            for (int nt = 0; nt < 8; ++nt)
                mma16816(C[nt], a0, a1, a2, a3, B0[kk][nt], B1[kk][nt]);
        }

        const float s = g_dinv[rb >> 6];
        __half* oa = out + (size_t)(rb + g) * 64 + t * 2;
        __half* ob = out + (size_t)(rb + g + 8) * 64 + t * 2;
#pragma unroll
        for (int nt = 0; nt < 8; ++nt) {
            *reinterpret_cast<__half2*>(oa + nt * 8) =
                __floats2half2_rn(C[nt][0] * s, C[nt][1] * s);
            *reinterpret_cast<__half2*>(ob + nt * 8) =
                __floats2half2_rn(C[nt][2] * s, C[nt][3] * s);
        }
    }
}

// ---------------- HMMA final GEMM K=64 + bias + tanh, transposed store
__global__ __launch_bounds__(128) void hgemm_final_kernel(
    const __half* __restrict__ in, const float* __restrict__ bias,
    float* __restrict__ out)
{
    const int lane = threadIdx.x & 31;
    const int g = lane >> 2, t = lane & 3;

    uint32_t B0[4][8], B1[4][8];
    const uint32_t* wp = reinterpret_cast<const uint32_t*>(g_Wft);
#pragma unroll
    for (int kk = 0; kk < 4; ++kk)
#pragma unroll
        for (int nt = 0; nt < 8; ++nt) {
            B0[kk][nt] = wp[((nt * 8 + g) * 64 + kk * 16 + t * 2) >> 1];
            B1[kk][nt] = wp[((nt * 8 + g) * 64 + kk * 16 + 8 + t * 2) >> 1];
        }
    float2 bv[8];
#pragma unroll
    for (int nt = 0; nt < 8; ++nt)
        bv[nt] = *reinterpret_cast<const float2*>(bias + nt * 8 + t * 2);

    const int warp = (blockIdx.x * blockDim.x + threadIdx.x) >> 5;
    const int nw   = (gridDim.x * blockDim.x) >> 5;
    for (int tile = warp; tile < NTILES; tile += nw) {
        const int rb = tile * 16;
        const uint32_t* ap = reinterpret_cast<const uint32_t*>(in + (size_t)rb * 64);

        float C[8][4];
#pragma unroll
        for (int nt = 0; nt < 8; ++nt) { C[nt][0] = C[nt][1] = C[nt][2] = C[nt][3] = 0.f; }
#pragma unroll
        for (int kk = 0; kk < 4; ++kk) {
            uint32_t a0 = ap[(g * 64 + kk * 16 + t * 2) >> 1];
            uint32_t a1 = ap[((g + 8) * 64 + kk * 16 + t * 2) >> 1];
            uint32_t a2 = ap[(g * 64 + kk * 16 + 8 + t * 2) >> 1];
            uint32_t a3 = ap[((g + 8) * 64 + kk * 16 + 8 + t * 2) >> 1];
#pragma unroll
            for (int nt = 0; nt < 8; ++nt)
                mma16816(C[nt], a0, a1, a2, a3, B0[kk][nt], B1[kk][nt]);
        }

        const int ra = rb + g, rbw = rb + g + 8;
        const int na = ra >> 6, ba = ra & 63;
        const int nb = rbw >> 6, bb = rbw & 63;
        float* oa = out + (size_t)ba * (NA * HD) + (size_t)na * 64 + t * 2;
        float* ob = out + (size_t)bb * (NA * HD) + (size_t)nb * 64 + t * 2;
#pragma unroll
        for (int nt = 0; nt < 8; ++nt) {
            *reinterpret_cast<float2*>(oa + nt * 8) =
                make_float2(tanhf(C[nt][0] + bv[nt].x), tanhf(C[nt][1] + bv[nt].y));
            *reinterpret_cast<float2*>(ob + nt * 8) =
                make_float2(tanhf(C[nt][2] + bv[nt].x), tanhf(C[nt][3] + bv[nt].y));
        }
    }
}

// ---------------------------------------------------------------------------

extern "C" void kernel_launch(void* const* d_in, const int* in_sizes, int n_in,
                              void* d_out, int out_size)
{
    const float* state = (const float*)d_in[0];
    const int*   ei    = (const int*)d_in[1];
    const float* W1  = (const float*)d_in[5];
    const float* b1  = (const float*)d_in[6];
    const float* W2  = (const float*)d_in[7];
    const float* b2  = (const float*)d_in[8];
    const float* W3  = (const float*)d_in[9];
    const float* b3  = (const float*)d_in[10];
    const float* g1  = (const float*)d_in[11];
    const float* be1 = (const float*)d_in[12];
    const float* g3  = (const float*)d_in[13];
    const float* be3 = (const float*)d_in[14];
    const float* Wf  = (const float*)d_in[15];
    const float* bf  = (const float*)d_in[16];
    float* out = (float*)d_out;

    const int E = in_sizes[1] / 2;

    __half *pH1h, *pH2h, *pH3h, *pPre, *pX, *pAX;
    cudaGetSymbolAddress((void**)&pH1h, g_h1h);
    cudaGetSymbolAddress((void**)&pH2h, g_h2h);
    cudaGetSymbolAddress((void**)&pH3h, g_h3h);
    cudaGetSymbolAddress((void**)&pPre, g_pre);
    cudaGetSymbolAddress((void**)&pX,   g_X);
    cudaGetSymbolAddress((void**)&pAX,  g_AX);

    __half* pW3t;
    cudaGetSymbolAddress((void**)&pW3t, g_W3t);
    int* pDeg;
    cudaGetSymbolAddress((void**)&pDeg, g_deg);

    // graph preprocessing (CSR by dst; self-loops emitted by scan)
    cudaMemsetAsync(pDeg, 0, NA * sizeof(int));
    count_kernel<<<(E + 255) / 256, 256>>>(ei, E);
    scan_kernel<<<1, 1024>>>();                       // rowptr/fillptr + dinv + self loops
    fill_kernel<<<(E + 255) / 256, 256>>>(ei, E);

    // transpose input (+ weight fp16 transposes, merged)
    transpose_prep_kernel<<<(NA * CF + 255) / 256, 256>>>(state, W1, W2, W3, Wf);

    // conv1 = (A x) W1, + fused W2 GEMM producing conv2's pre-agg operand
    agg16_kernel<<<NA, 128>>>(pX, pAX);
    hgemm16_ln_w2_kernel<<<4736, 128>>>(pAX, b1, g1, be1, pH1h, pPre);

    // conv2: h2 = leaky(A pre + b2) + h1
    aggH_kernel<1><<<dim3(NA, 2), 128>>>(pPre, pH2h, b2, nullptr, nullptr);

    // conv3: h3 = leaky(LN(A (h2 W3) + b3)) + h1
    hgemm64_kernel<<<4736, 128>>>(pH2h, pW3t, pPre);
    aggH_kernel<2><<<dim3(NA, 2), 128>>>(pPre, pH3h, b3, g3, be3);

    // out = tanh(h3 Wf + bf), transposed back to [B, N*H]
    hgemm_final_kernel<<<4736, 128>>>(pH3h, bf, out);
}

// round 11
// speedup vs baseline: 2.5967x; 1.0232x over previous
#include <cuda_runtime.h>
#include <cuda_fp16.h>
#include <stdint.h>
#include <math.h>

// ---------------------------------------------------------------------------
// GNN_Encoder: 3x GCNConv (self-loops, sym-norm) + LN/leaky/residual + tanh
// B=64, N=10000, F=16, H=64, E=320000
// R10: R9 + vectorized transpose (float4 per (n,b) row) + weight prep merged
//      into count_kernel. HMMA GEMMs (W2 fused into conv1 GEMM), fp16
//      inter-stage buffers, fused epilogues.
// ---------------------------------------------------------------------------

namespace {
constexpr int NA = 10000;
constexpr int NF = 16;
constexpr int HD = 64;
constexpr int BT = 64;
constexpr int MR = NA * BT;        // 640000 rows ([node][batch] major)
constexpr int CH = BT * HD;        // 4096 hidden cols per node
constexpr int CF = BT * NF;        // 1024 input cols per node
constexpr int EMAX = 330000;
constexpr int NTILES = MR / 16;    // 40000 16-row mma tiles
}

// scratch (device globals; no allocation allowed)
__device__ __align__(256) __half g_h1h[MR * HD];      // h1 fp16
__device__ __align__(256) __half g_h2h[MR * HD];      // h2 fp16
__device__ __align__(256) __half g_h3h[MR * HD];      // h3 fp16
__device__ __align__(256) __half g_pre[MR * HD];      // pre-agg operand fp16
__device__ __align__(256) __half g_X[NA * CF];        // pre-scaled input fp16
__device__ __align__(256) __half g_AX[NA * CF];       // A·x fp16
__device__ __half g_W1t[HD * NF];   // [n][k] transposed fp16 weights
__device__ __half g_W2t[HD * HD];
__device__ __half g_W3t[HD * HD];
__device__ __half g_Wft[HD * HD];
__device__ int   g_deg[NA];
__device__ float g_dinv[NA];
__device__ int   g_rowptr[NA + 1];
__device__ int   g_fillptr[NA];
__device__ int   g_col[EMAX];

__device__ __forceinline__ float leaky(float x) {
    return x >= 0.f ? x : 0.01f * x;
}

__device__ __forceinline__ void mma16816(float c[4],
    uint32_t a0, uint32_t a1, uint32_t a2, uint32_t a3,
    uint32_t b0, uint32_t b1)
{
    asm volatile(
        "mma.sync.aligned.m16n8k16.row.col.f32.f16.f16.f32 "
        "{%0,%1,%2,%3},{%4,%5,%6,%7},{%8,%9},{%0,%1,%2,%3};"
        : "+f"(c[0]), "+f"(c[1]), "+f"(c[2]), "+f"(c[3])
        : "r"(a0), "r"(a1), "r"(a2), "r"(a3), "r"(b0), "r"(b1));
}

// ---------------- graph preprocessing ----------------

// g_deg was memset to 0; count edges by dst. First 4096 threads also convert
// weights to fp16 transposed [n][k] (independent work, saves a launch).
__global__ void count_kernel(const int* __restrict__ ei, int E,
                             const float* __restrict__ W1,
                             const float* __restrict__ W2,
                             const float* __restrict__ W3,
                             const float* __restrict__ Wf)
{
    int i = blockIdx.x * blockDim.x + threadIdx.x;
    if (i < E) atomicAdd(&g_deg[ei[E + i]], 1);
    if (i < HD * HD) {
        int n = i / HD, k = i % HD;
        g_W2t[i] = __float2half(W2[k * HD + n]);
        g_W3t[i] = __float2half(W3[k * HD + n]);
        g_Wft[i] = __float2half(Wf[k * HD + n]);
        if (i < HD * NF) {
            int n1 = i / NF, k1 = i % NF;
            g_W1t[i] = __float2half(W1[k1 * HD + n1]);
        }
    }
}

// scan of (deg+1) -> rowptr, fillptr=rowptr+1, self-loop col entry, dinv
__global__ __launch_bounds__(1024) void scan_kernel() {
    __shared__ int warp_tot[32];
    const int tid  = threadIdx.x;
    const int lane = tid & 31;
    const int wid  = tid >> 5;
    const int base = tid * 10;

    int v[10];
    int run = 0;
#pragma unroll
    for (int k = 0; k < 10; ++k) {
        int i = base + k;
        int x = (i < NA) ? (g_deg[i] + 1) : 0;   // +1 self loop
        if (i < NA) g_dinv[i] = rsqrtf((float)x);
        run += x;
        v[k] = run;
    }
    int s = run;
#pragma unroll
    for (int off = 1; off < 32; off <<= 1) {
        int y = __shfl_up_sync(0xffffffffu, s, off);
        if (lane >= off) s += y;
    }
    if (lane == 31) warp_tot[wid] = s;
    __syncthreads();
    if (wid == 0) {
        int w = warp_tot[lane];
#pragma unroll
        for (int off = 1; off < 32; off <<= 1) {
            int y = __shfl_up_sync(0xffffffffu, w, off);
            if (lane >= off) w += y;
        }
        warp_tot[lane] = w;
    }
    __syncthreads();
    const int warp_off = (wid == 0) ? 0 : warp_tot[wid - 1];
    const int excl = warp_off + (s - run);
    if (tid == 0) g_rowptr[0] = 0;
#pragma unroll
    for (int k = 0; k < 10; ++k) {
        int i = base + k;
        if (i < NA) {
            int rbeg = excl + (k ? v[k - 1] : 0);
            g_rowptr[i + 1] = excl + v[k];
            g_col[rbeg]     = i;           // self loop first
            g_fillptr[i]    = rbeg + 1;    // edges after it
        }
    }
}

__global__ void fill_kernel(const int* __restrict__ ei, int E) {
    int i = blockIdx.x * blockDim.x + threadIdx.x;
    if (i < E) {
        int d = ei[E + i];
        int pos = atomicAdd(&g_fillptr[d], 1);
        g_col[pos] = ei[i];
    }
}

// ---------------- transpose + pre-scale (vectorized):
// one thread per (n, b): 16 floats read as 4x float4, 16 halves written as 2x float4
__global__ void transpose_kernel(const float* __restrict__ state) {
    int i = blockIdx.x * blockDim.x + threadIdx.x;
    if (i >= NA * BT) return;
    const int n = i >> 6, b = i & 63;
    const float4* sp = reinterpret_cast<const float4*>(
        state + (size_t)b * (NA * NF) + n * NF);
    const float sc = g_dinv[n];
    __half2 o[8];
#pragma unroll
    for (int q = 0; q < 4; ++q) {
        float4 u = sp[q];
        o[2 * q]     = __floats2half2_rn(u.x * sc, u.y * sc);
        o[2 * q + 1] = __floats2half2_rn(u.z * sc, u.w * sc);
    }
    float4* dp = reinterpret_cast<float4*>(g_X + (size_t)n * CF + b * NF);
    dp[0] = reinterpret_cast<const float4*>(o)[0];
    dp[1] = reinterpret_cast<const float4*>(o)[1];
}

// ---------------- conv1 aggregation: AX[d] = dinv[d] * sum_s X[s] (fp16 out)
__global__ __launch_bounds__(128) void agg16_kernel(
    const __half* __restrict__ src, __half* __restrict__ dst)
{
    const int d = blockIdx.x;
    const int c = threadIdx.x * 8;
    float acc[8];
#pragma unroll
    for (int k = 0; k < 8; ++k) acc[k] = 0.f;

    const int beg = g_rowptr[d], end = g_rowptr[d + 1];
#pragma unroll 4
    for (int j = beg; j < end; ++j) {
        const int s = g_col[j];
        float4 u = *reinterpret_cast<const float4*>(src + (size_t)s * CF + c);
        const __half2* h = reinterpret_cast<const __half2*>(&u);
#pragma unroll
        for (int k = 0; k < 4; ++k) {
            float2 f = __half22float2(h[k]);
            acc[2 * k]     += f.x;
            acc[2 * k + 1] += f.y;
        }
    }
    const float sc = g_dinv[d];
    __half2 o[4];
#pragma unroll
    for (int k = 0; k < 4; ++k)
        o[k] = __floats2half2_rn(acc[2 * k] * sc, acc[2 * k + 1] * sc);
    *reinterpret_cast<float4*>(dst + (size_t)d * CF + c) =
        *reinterpret_cast<const float4*>(o);
}

// ---------------- hidden aggregation (4096 fp16 cols, 2 chunks of 2048)
// MODE 1: +b2, leaky, +h1 -> h2 fp16
// MODE 2: +b3, LN(g3,be3), leaky, +h1 -> h3 fp16
template <int MODE>
__global__ __launch_bounds__(128) void aggH_kernel(
    const __half* __restrict__ src, __half* __restrict__ dst,
    const float* __restrict__ bias,
    const float* __restrict__ gma, const float* __restrict__ bta)
{
    const int d  = blockIdx.x;
    const int c0 = blockIdx.y * 2048 + threadIdx.x * 16;
    const int f0 = c0 & 63;

    float acc[16];
#pragma unroll
    for (int k = 0; k < 16; ++k) acc[k] = 0.f;

    const int beg = g_rowptr[d], end = g_rowptr[d + 1];
#pragma unroll 4
    for (int j = beg; j < end; ++j) {
        const int s = g_col[j];
        const __half* row = src + (size_t)s * CH + c0;
        float4 u0 = *reinterpret_cast<const float4*>(row);
        float4 u1 = *reinterpret_cast<const float4*>(row + 8);
        const __half2* h0 = reinterpret_cast<const __half2*>(&u0);
        const __half2* h1 = reinterpret_cast<const __half2*>(&u1);
#pragma unroll
        for (int k = 0; k < 4; ++k) {
            float2 a = __half22float2(h0[k]);
            float2 b = __half22float2(h1[k]);
            acc[2 * k]         += a.x;
            acc[2 * k + 1]     += a.y;
            acc[8 + 2 * k]     += b.x;
            acc[8 + 2 * k + 1] += b.y;
        }
    }

    const float sc = g_dinv[d];
    float v[16];
#pragma unroll
    for (int k = 0; k < 16; ++k) v[k] = fmaf(acc[k], sc, bias[f0 + k]);

    // fp16 h1 residual (16 halves = 2x float4)
    const __half* h1p = g_h1h + (size_t)d * CH + c0;
    float4 r0 = *reinterpret_cast<const float4*>(h1p);
    float4 r1 = *reinterpret_cast<const float4*>(h1p + 8);
    float h1v[16];
    {
        const __half2* p0 = reinterpret_cast<const __half2*>(&r0);
        const __half2* p1 = reinterpret_cast<const __half2*>(&r1);
#pragma unroll
        for (int k = 0; k < 4; ++k) {
            float2 a = __half22float2(p0[k]);
            float2 b = __half22float2(p1[k]);
            h1v[2 * k]         = a.x;
            h1v[2 * k + 1]     = a.y;
            h1v[8 + 2 * k]     = b.x;
            h1v[8 + 2 * k + 1] = b.y;
        }
    }

    float out[16];
    if (MODE == 1) {
#pragma unroll
        for (int k = 0; k < 16; ++k) out[k] = leaky(v[k]) + h1v[k];
    } else {
        float s1 = 0.f, s2 = 0.f;
#pragma unroll
        for (int k = 0; k < 16; ++k) { s1 += v[k]; s2 += v[k] * v[k]; }
        s1 += __shfl_xor_sync(0xffffffffu, s1, 1);
        s2 += __shfl_xor_sync(0xffffffffu, s2, 1);
        s1 += __shfl_xor_sync(0xffffffffu, s1, 2);
        s2 += __shfl_xor_sync(0xffffffffu, s2, 2);
        const float mean = s1 * (1.f / 64.f);
        const float var  = fmaf(s2, 1.f / 64.f, -mean * mean);
        const float rs   = rsqrtf(var + 1e-5f);
#pragma unroll
        for (int k = 0; k < 16; ++k)
            out[k] = leaky(fmaf((v[k] - mean) * rs, gma[f0 + k], bta[f0 + k])) + h1v[k];
    }

    __half2 o[8];
#pragma unroll
    for (int k = 0; k < 8; ++k)
        o[k] = __floats2half2_rn(out[2 * k], out[2 * k + 1]);
    float4* op = reinterpret_cast<float4*>(dst + (size_t)d * CH + c0);
    op[0] = reinterpret_cast<const float4*>(o)[0];
    op[1] = reinterpret_cast<const float4*>(o)[1];
}

// ---------------- HMMA GEMM K=16 + bias + LN + leaky -> h1 fp16,
// then fused W2 GEMM on the in-register h1 (C-frag == A-frag layout),
// epilogue * dinv[node] -> g_pre fp16
__global__ __launch_bounds__(128) void hgemm16_ln_w2_kernel(
    const __half* __restrict__ in, const float* __restrict__ bias,
    const float* __restrict__ gma, const float* __restrict__ bta,
    __half* __restrict__ out_h1, __half* __restrict__ out_pre)
{
    const int lane = threadIdx.x & 31;
    const int g = lane >> 2, t = lane & 3;

    // W1 B-frags (K=16: one k-step), col n = nt*8+g, k = t*2 (+8)
    uint32_t B0[8], B1[8];
    {
        const uint32_t* wp = reinterpret_cast<const uint32_t*>(g_W1t);
#pragma unroll
        for (int nt = 0; nt < 8; ++nt) {
            B0[nt] = wp[((nt * 8 + g) * 16 + t * 2) >> 1];
            B1[nt] = wp[((nt * 8 + g) * 16 + 8 + t * 2) >> 1];
        }
    }
    // W2 B-frags (K=64: 4 k-steps)
    uint32_t W20[4][8], W21[4][8];
    {
        const uint32_t* wp = reinterpret_cast<const uint32_t*>(g_W2t);
#pragma unroll
        for (int kk = 0; kk < 4; ++kk)
#pragma unroll
            for (int nt = 0; nt < 8; ++nt) {
                W20[kk][nt] = wp[((nt * 8 + g) * 64 + kk * 16 + t * 2) >> 1];
                W21[kk][nt] = wp[((nt * 8 + g) * 64 + kk * 16 + 8 + t * 2) >> 1];
            }
    }

    const int warp = (blockIdx.x * blockDim.x + threadIdx.x) >> 5;
    const int nw   = (gridDim.x * blockDim.x) >> 5;
    for (int tile = warp; tile < NTILES; tile += nw) {
        const int rb = tile * 16;
        const uint32_t* ap = reinterpret_cast<const uint32_t*>(in + (size_t)rb * 16);
        uint32_t a0 = ap[(g * 16 + t * 2) >> 1];
        uint32_t a1 = ap[((g + 8) * 16 + t * 2) >> 1];
        uint32_t a2 = ap[(g * 16 + 8 + t * 2) >> 1];
        uint32_t a3 = ap[((g + 8) * 16 + 8 + t * 2) >> 1];

        float C[8][4];
#pragma unroll
        for (int nt = 0; nt < 8; ++nt) { C[nt][0] = C[nt][1] = C[nt][2] = C[nt][3] = 0.f; }
#pragma unroll
        for (int nt = 0; nt < 8; ++nt)
            mma16816(C[nt], a0, a1, a2, a3, B0[nt], B1[nt]);

        // bias + LN + leaky epilogue (params loaded per tile to cap registers)
        float va[16], vb[16];
#pragma unroll
        for (int nt = 0; nt < 8; ++nt) {
            float2 bv = *reinterpret_cast<const float2*>(bias + nt * 8 + t * 2);
            va[2 * nt]     = C[nt][0] + bv.x;
            va[2 * nt + 1] = C[nt][1] + bv.y;
            vb[2 * nt]     = C[nt][2] + bv.x;
            vb[2 * nt + 1] = C[nt][3] + bv.y;
        }
        float s1a = 0.f, s2a = 0.f, s1b = 0.f, s2b = 0.f;
#pragma unroll
        for (int k = 0; k < 16; ++k) {
            s1a += va[k]; s2a += va[k] * va[k];
            s1b += vb[k]; s2b += vb[k] * vb[k];
        }
#pragma unroll
        for (int off = 1; off <= 2; off <<= 1) {
            s1a += __shfl_xor_sync(0xffffffffu, s1a, off);
            s2a += __shfl_xor_sync(0xffffffffu, s2a, off);
            s1b += __shfl_xor_sync(0xffffffffu, s1b, off);
            s2b += __shfl_xor_sync(0xffffffffu, s2b, off);
        }
        const float ma = s1a * (1.f / 64.f);
        const float ra = rsqrtf(fmaf(s2a, 1.f / 64.f, -ma * ma) + 1e-5f);
        const float mb = s1b * (1.f / 64.f);
        const float rbv = rsqrtf(fmaf(s2b, 1.f / 64.f, -mb * mb) + 1e-5f);

        // h1 as fp16 packs: ha[nt] = cols (8nt+2t, +1) of row g; hb: row g+8
        uint32_t ha[8], hb[8];
#pragma unroll
        for (int nt = 0; nt < 8; ++nt) {
            float2 gv = *reinterpret_cast<const float2*>(gma + nt * 8 + t * 2);
            float2 ev = *reinterpret_cast<const float2*>(bta + nt * 8 + t * 2);
            float x0 = leaky(fmaf((va[2 * nt]     - ma) * ra, gv.x, ev.x));
            float x1 = leaky(fmaf((va[2 * nt + 1] - ma) * ra, gv.y, ev.y));
            float y0 = leaky(fmaf((vb[2 * nt]     - mb) * rbv, gv.x, ev.x));
            float y1 = leaky(fmaf((vb[2 * nt + 1] - mb) * rbv, gv.y, ev.y));
            __half2 hx = __floats2half2_rn(x0, x1);
            __half2 hy = __floats2half2_rn(y0, y1);
            ha[nt] = *reinterpret_cast<const uint32_t*>(&hx);
            hb[nt] = *reinterpret_cast<const uint32_t*>(&hy);
        }
        // store h1
        __half* oa16 = out_h1 + (size_t)(rb + g) * 64 + t * 2;
        __half* ob16 = out_h1 + (size_t)(rb + g + 8) * 64 + t * 2;
#pragma unroll
        for (int nt = 0; nt < 8; ++nt) {
            *reinterpret_cast<uint32_t*>(oa16 + nt * 8) = ha[nt];
            *reinterpret_cast<uint32_t*>(ob16 + nt * 8) = hb[nt];
        }

        // fused W2 GEMM: A-frag for k-block kk is (ha[2kk], hb[2kk], ha[2kk+1], hb[2kk+1])
        float C2[8][4];
#pragma unroll
        for (int nt = 0; nt < 8; ++nt) { C2[nt][0] = C2[nt][1] = C2[nt][2] = C2[nt][3] = 0.f; }
#pragma unroll
        for (int kk = 0; kk < 4; ++kk) {
#pragma unroll
            for (int nt = 0; nt < 8; ++nt)
                mma16816(C2[nt], ha[2 * kk], hb[2 * kk], ha[2 * kk + 1], hb[2 * kk + 1],
                         W20[kk][nt], W21[kk][nt]);
        }

        const float s = g_dinv[rb >> 6];
        __half* pa = out_pre + (size_t)(rb + g) * 64 + t * 2;
        __half* pb = out_pre + (size_t)(rb + g + 8) * 64 + t * 2;
#pragma unroll
        for (int nt = 0; nt < 8; ++nt) {
            *reinterpret_cast<__half2*>(pa + nt * 8) =
                __floats2half2_rn(C2[nt][0] * s, C2[nt][1] * s);
            *reinterpret_cast<__half2*>(pb + nt * 8) =
                __floats2half2_rn(C2[nt][2] * s, C2[nt][3] * s);
        }
    }
}

// ---------------- HMMA GEMM K=64, epilogue * dinv[node] -> fp16
__global__ __launch_bounds__(128) void hgemm64_kernel(
    const __half* __restrict__ in, const __half* __restrict__ Wt,
    __half* __restrict__ out)
{
    const int lane = threadIdx.x & 31;
    const int g = lane >> 2, t = lane & 3;

    uint32_t B0[4][8], B1[4][8];
    const uint32_t* wp = reinterpret_cast<const uint32_t*>(Wt);
#pragma unroll
    for (int kk = 0; kk < 4; ++kk)
#pragma unroll
        for (int nt = 0; nt < 8; ++nt) {
            B0[kk][nt] = wp[((nt * 8 + g) * 64 + kk * 16 + t * 2) >> 1];
            B1[kk][nt] = wp[((nt * 8 + g) * 64 + kk * 16 + 8 + t * 2) >> 1];
        }

    const int warp = (blockIdx.x * blockDim.x + threadIdx.x) >> 5;
    const int nw   = (gridDim.x * blockDim.x) >> 5;
    for (int tile = warp; tile < NTILES; tile += nw) {
        const int rb = tile * 16;
        const uint32_t* ap = reinterpret_cast<const uint32_t*>(in + (size_t)rb * 64);

        float C[8][4];
#pragma unroll
        for (int nt = 0; nt < 8; ++nt) { C[nt][0] = C[nt][1] = C[nt][2] = C[nt][3] = 0.f; }
#pragma unroll
        for (int kk = 0; kk < 4; ++kk) {
            uint32_t a0 = ap[(g * 64 + kk * 16 + t * 2) >> 1];
            uint32_t a1 = ap[((g + 8) * 64 + kk * 16 + t * 2) >> 1];
            uint32_t a2 = ap[(g * 64 + kk * 16 + 8 + t * 2) >> 1];
            uint32_t a3 = ap[((g + 8) * 64 + kk * 16 + 8 + t * 2) >> 1];
#pragma unroll
            for (int nt = 0; nt < 8; ++nt)
                mma16816(C[nt], a0, a1, a2, a3, B0[kk][nt], B1[kk][nt]);
        }

        const float s = g_dinv[rb >> 6];
        __half* oa = out + (size_t)(rb + g) * 64 + t * 2;
        __half* ob = out + (size_t)(rb + g + 8) * 64 + t * 2;
#pragma unroll
        for (int nt = 0; nt < 8; ++nt) {
            *reinterpret_cast<__half2*>(oa + nt * 8) =
                __floats2half2_rn(C[nt][0] * s, C[nt][1] * s);
            *reinterpret_cast<__half2*>(ob + nt * 8) =
                __floats2half2_rn(C[nt][2] * s, C[nt][3] * s);
        }
    }
}

// ---------------- HMMA final GEMM K=64 + bias + tanh, transposed store
__global__ __launch_bounds__(128) void hgemm_final_kernel(
    const __half* __restrict__ in, const float* __restrict__ bias,
    float* __restrict__ out)
{
    const int lane = threadIdx.x & 31;
    const int g = lane >> 2, t = lane & 3;

    uint32_t B0[4][8], B1[4][8];
    const uint32_t* wp = reinterpret_cast<const uint32_t*>(g_Wft);
#pragma unroll
    for (int kk = 0; kk < 4; ++kk)
#pragma unroll
        for (int nt = 0; nt < 8; ++nt) {
            B0[kk][nt] = wp[((nt * 8 + g) * 64 + kk * 16 + t * 2) >> 1];
            B1[kk][nt] = wp[((nt * 8 + g) * 64 + kk * 16 + 8 + t * 2) >> 1];
        }
    float2 bv[8];
#pragma unroll
    for (int nt = 0; nt < 8; ++nt)
        bv[nt] = *reinterpret_cast<const float2*>(bias + nt * 8 + t * 2);

    const int warp = (blockIdx.x * blockDim.x + threadIdx.x) >> 5;
    const int nw   = (gridDim.x * blockDim.x) >> 5;
    for (int tile = warp; tile < NTILES; tile += nw) {
        const int rb = tile * 16;
        const uint32_t* ap = reinterpret_cast<const uint32_t*>(in + (size_t)rb * 64);

        float C[8][4];
#pragma unroll
        for (int nt = 0; nt < 8; ++nt) { C[nt][0] = C[nt][1] = C[nt][2] = C[nt][3] = 0.f; }
#pragma unroll
        for (int kk = 0; kk < 4; ++kk) {
            uint32_t a0 = ap[(g * 64 + kk * 16 + t * 2) >> 1];
            uint32_t a1 = ap[((g + 8) * 64 + kk * 16 + t * 2) >> 1];
            uint32_t a2 = ap[(g * 64 + kk * 16 + 8 + t * 2) >> 1];
            uint32_t a3 = ap[((g + 8) * 64 + kk * 16 + 8 + t * 2) >> 1];
#pragma unroll
            for (int nt = 0; nt < 8; ++nt)
                mma16816(C[nt], a0, a1, a2, a3, B0[kk][nt], B1[kk][nt]);
        }

        const int ra = rb + g, rbw = rb + g + 8;
        const int na = ra >> 6, ba = ra & 63;
        const int nb = rbw >> 6, bb = rbw & 63;
        float* oa = out + (size_t)ba * (NA * HD) + (size_t)na * 64 + t * 2;
        float* ob = out + (size_t)bb * (NA * HD) + (size_t)nb * 64 + t * 2;
#pragma unroll
        for (int nt = 0; nt < 8; ++nt) {
            *reinterpret_cast<float2*>(oa + nt * 8) =
                make_float2(tanhf(C[nt][0] + bv[nt].x), tanhf(C[nt][1] + bv[nt].y));
            *reinterpret_cast<float2*>(ob + nt * 8) =
                make_float2(tanhf(C[nt][2] + bv[nt].x), tanhf(C[nt][3] + bv[nt].y));
        }
    }
}

// ---------------------------------------------------------------------------

extern "C" void kernel_launch(void* const* d_in, const int* in_sizes, int n_in,
                              void* d_out, int out_size)
{
    const float* state = (const float*)d_in[0];
    const int*   ei    = (const int*)d_in[1];
    const float* W1  = (const float*)d_in[5];
    const float* b1  = (const float*)d_in[6];
    const float* W2  = (const float*)d_in[7];
    const float* b2  = (const float*)d_in[8];
    const float* W3  = (const float*)d_in[9];
    const float* b3  = (const float*)d_in[10];
    const float* g1  = (const float*)d_in[11];
    const float* be1 = (const float*)d_in[12];
    const float* g3  = (const float*)d_in[13];
    const float* be3 = (const float*)d_in[14];
    const float* Wf  = (const float*)d_in[15];
    const float* bf  = (const float*)d_in[16];
    float* out = (float*)d_out;

    const int E = in_sizes[1] / 2;

    __half *pH1h, *pH2h, *pH3h, *pPre, *pX, *pAX;
    cudaGetSymbolAddress((void**)&pH1h, g_h1h);
    cudaGetSymbolAddress((void**)&pH2h, g_h2h);
    cudaGetSymbolAddress((void**)&pH3h, g_h3h);
    cudaGetSymbolAddress((void**)&pPre, g_pre);
    cudaGetSymbolAddress((void**)&pX,   g_X);
    cudaGetSymbolAddress((void**)&pAX,  g_AX);

    __half* pW3t;
    cudaGetSymbolAddress((void**)&pW3t, g_W3t);
    int* pDeg;
    cudaGetSymbolAddress((void**)&pDeg, g_deg);

    // graph preprocessing (CSR by dst; self-loops emitted by scan),
    // weight fp16 prep merged into count
    cudaMemsetAsync(pDeg, 0, NA * sizeof(int));
    count_kernel<<<(E + 255) / 256, 256>>>(ei, E, W1, W2, W3, Wf);
    scan_kernel<<<1, 1024>>>();                       // rowptr/fillptr + dinv + self loops
    fill_kernel<<<(E + 255) / 256, 256>>>(ei, E);

    // transpose input (vectorized: one thread per (node, batch))
    transpose_kernel<<<(NA * BT + 255) / 256, 256>>>(state);

    // conv1 = (A x) W1, + fused W2 GEMM producing conv2's pre-agg operand
    agg16_kernel<<<NA, 128>>>(pX, pAX);
    hgemm16_ln_w2_kernel<<<4736, 128>>>(pAX, b1, g1, be1, pH1h, pPre);

    // conv2: h2 = leaky(A pre + b2) + h1
    aggH_kernel<1><<<dim3(NA, 2), 128>>>(pPre, pH2h, b2, nullptr, nullptr);

    // conv3: h3 = leaky(LN(A (h2 W3) + b3)) + h1
    hgemm64_kernel<<<4736, 128>>>(pH2h, pW3t, pPre);
    aggH_kernel<2><<<dim3(NA, 2), 128>>>(pPre, pH3h, b3, g3, be3);

    // out = tanh(h3 Wf + bf), transposed back to [B, N*H]
    hgemm_final_kernel<<<4736, 128>>>(pH3h, bf, out);
}